// round 2
// baseline (speedup 1.0000x reference)
#include <cuda_runtime.h>
#include <cuda_bf16.h>
#include <cstdint>

// ---------------------------------------------------------------------------
// Problem constants (B=2, L=1024, D_MODEL=1024, D_INNER=2048, N=16, CONV=4)
// ---------------------------------------------------------------------------
#define TOKENS   2048      // B*L
#define DMODEL   1024
#define DINNER   2048
#define DSTATE   16
#define DCONV    4

// ---------------------------------------------------------------------------
// Scratch buffers (static device globals; no allocation allowed)
// ---------------------------------------------------------------------------
__device__ float g_xn   [TOKENS * DMODEL];        // 8 MB  rmsnorm output
__device__ float g_xz   [TOKENS * 2 * DINNER];    // 32 MB xz = xn @ W_in^T
__device__ float g_xc   [TOKENS * DINNER];        // 16 MB conv+silu output (x_ssm)
__device__ float g_Bp   [TOKENS * DSTATE];
__device__ float g_Cp   [TOKENS * DSTATE];
__device__ float g_dt   [TOKENS];
__device__ float g_delta[TOKENS * DINNER];        // 16 MB
__device__ float g_y    [TOKENS * DINNER];        // 16 MB gated scan output

// ---------------------------------------------------------------------------
// RMSNorm: one block per token
// ---------------------------------------------------------------------------
__global__ void rmsnorm_kernel(const float* __restrict__ x,
                               const float* __restrict__ w,
                               float* __restrict__ out) {
    int t = blockIdx.x;
    const float4* xr = (const float4*)(x + (size_t)t * DMODEL);
    float4 v = xr[threadIdx.x];                       // 256 threads * 4 = 1024
    float ss = v.x*v.x + v.y*v.y + v.z*v.z + v.w*v.w;
    #pragma unroll
    for (int o = 16; o > 0; o >>= 1) ss += __shfl_xor_sync(0xffffffffu, ss, o);
    __shared__ float sred[8];
    __shared__ float sinv;
    int lane = threadIdx.x & 31, wid = threadIdx.x >> 5;
    if (lane == 0) sred[wid] = ss;
    __syncthreads();
    if (threadIdx.x == 0) {
        float tot = 0.f;
        #pragma unroll
        for (int i = 0; i < 8; i++) tot += sred[i];
        sinv = rsqrtf(tot * (1.0f / DMODEL) + 1e-6f);
    }
    __syncthreads();
    float inv = sinv;
    const float4* wr = (const float4*)w;
    float4 wv = wr[threadIdx.x];
    float4 o4 = make_float4(v.x*inv*wv.x, v.y*inv*wv.y, v.z*inv*wv.z, v.w*inv*wv.w);
    ((float4*)(out + (size_t)t * DMODEL))[threadIdx.x] = o4;
}

// ---------------------------------------------------------------------------
// SGEMM: C[m][n] = sum_k A[m*K+k] * B[n*K+k]  (+ Res[m*N+n])
// 128x128 block tile, BK=8, 256 threads, 8x8 per thread, reg double-buffer.
// ---------------------------------------------------------------------------
#define BM 128
#define BN 128
#define BKK 8
#define TM 8
#define TN 8

__global__ __launch_bounds__(256, 2)
void sgemm_tt(const float* __restrict__ A, const float* __restrict__ B,
              float* __restrict__ C, const float* __restrict__ Res,
              int M, int N, int K) {
    __shared__ float As[BKK][BM];
    __shared__ float Bs[BKK][BN];
    int bm = blockIdx.y * BM;
    int bn = blockIdx.x * BN;
    int tid = threadIdx.x;
    int lrow = tid >> 1;
    int lk   = (tid & 1) * 4;
    int tx = tid & 15, ty = tid >> 4;

    const float* Aptr = A + (size_t)(bm + lrow) * K + lk;
    const float* Bptr = B + (size_t)(bn + lrow) * K + lk;

    float acc[TM][TN];
    #pragma unroll
    for (int i = 0; i < TM; i++)
        #pragma unroll
        for (int j = 0; j < TN; j++) acc[i][j] = 0.f;

    float4 av = *(const float4*)(Aptr);
    float4 bv = *(const float4*)(Bptr);

    for (int k0 = 0; k0 < K; k0 += BKK) {
        __syncthreads();
        As[lk+0][lrow] = av.x; As[lk+1][lrow] = av.y;
        As[lk+2][lrow] = av.z; As[lk+3][lrow] = av.w;
        Bs[lk+0][lrow] = bv.x; Bs[lk+1][lrow] = bv.y;
        Bs[lk+2][lrow] = bv.z; Bs[lk+3][lrow] = bv.w;
        __syncthreads();
        if (k0 + BKK < K) {
            av = *(const float4*)(Aptr + k0 + BKK);
            bv = *(const float4*)(Bptr + k0 + BKK);
        }
        #pragma unroll
        for (int k = 0; k < BKK; k++) {
            float a[TM], b[TN];
            *(float4*)(a)     = *(const float4*)&As[k][ty * TM];
            *(float4*)(a + 4) = *(const float4*)&As[k][ty * TM + 4];
            *(float4*)(b)     = *(const float4*)&Bs[k][tx * TN];
            *(float4*)(b + 4) = *(const float4*)&Bs[k][tx * TN + 4];
            #pragma unroll
            for (int i = 0; i < TM; i++)
                #pragma unroll
                for (int j = 0; j < TN; j++)
                    acc[i][j] = fmaf(a[i], b[j], acc[i][j]);
        }
    }

    #pragma unroll
    for (int i = 0; i < TM; i++) {
        int row = bm + ty * TM + i;
        float* crow = C + (size_t)row * N + bn + tx * TN;
        if (Res) {
            const float* rrow = Res + (size_t)row * N + bn + tx * TN;
            float4 r0 = *(const float4*)(rrow);
            float4 r1 = *(const float4*)(rrow + 4);
            float4 o0 = make_float4(acc[i][0]+r0.x, acc[i][1]+r0.y, acc[i][2]+r0.z, acc[i][3]+r0.w);
            float4 o1 = make_float4(acc[i][4]+r1.x, acc[i][5]+r1.y, acc[i][6]+r1.z, acc[i][7]+r1.w);
            *(float4*)(crow)     = o0;
            *(float4*)(crow + 4) = o1;
        } else {
            float4 o0 = make_float4(acc[i][0], acc[i][1], acc[i][2], acc[i][3]);
            float4 o1 = make_float4(acc[i][4], acc[i][5], acc[i][6], acc[i][7]);
            *(float4*)(crow)     = o0;
            *(float4*)(crow + 4) = o1;
        }
    }
}

// ---------------------------------------------------------------------------
// Depthwise causal conv (width 4) + bias + SiLU.  In: g_xz[:, 0:2048]
// ---------------------------------------------------------------------------
__global__ void conv_silu_kernel(const float* __restrict__ xz,
                                 const float* __restrict__ convw,
                                 const float* __restrict__ convb,
                                 float* __restrict__ xc) {
    int idx = blockIdx.x * 256 + threadIdx.x;     // over TOKENS*DINNER
    int d  = idx & (DINNER - 1);
    int bt = idx >> 11;
    int t  = bt & 1023;
    float4 w = *(const float4*)(convw + (size_t)d * 4);
    size_t base = (size_t)bt * (2 * DINNER) + d;
    float acc = convb[d];
    if (t >= 3) {
        acc = fmaf(xz[base - 3 * 2 * DINNER], w.x, acc);
        acc = fmaf(xz[base - 2 * 2 * DINNER], w.y, acc);
        acc = fmaf(xz[base - 1 * 2 * DINNER], w.z, acc);
        acc = fmaf(xz[base],                  w.w, acc);
    } else {
        float wj[4] = {w.x, w.y, w.z, w.w};
        #pragma unroll
        for (int j = 0; j < 4; j++) {
            int tt = t - 3 + j;
            if (tt >= 0) acc = fmaf(xz[base + (size_t)(j - 3) * 2 * DINNER], wj[j], acc);
        }
    }
    float s = acc / (1.f + __expf(-acc));         // silu
    xc[idx] = s;
}

// ---------------------------------------------------------------------------
// ssm projection: 33 dot products of length 2048 per token.
// blockDim = (33, 8): thread (j, ty) handles token blockIdx.x*8+ty, output j.
// ---------------------------------------------------------------------------
__global__ void ssm_proj_kernel(const float* __restrict__ xc,
                                const float* __restrict__ Wx,
                                float* __restrict__ Bp, float* __restrict__ Cp,
                                float* __restrict__ dt) {
    int token = blockIdx.x * 8 + threadIdx.y;
    int j = threadIdx.x;                          // 0..32
    const float4* xr = (const float4*)(xc + (size_t)token * DINNER);
    const float4* wr = (const float4*)(Wx + (size_t)j * DINNER);
    float acc = 0.f;
    #pragma unroll 8
    for (int k = 0; k < DINNER / 4; k++) {
        float4 a = xr[k];
        float4 w = wr[k];
        acc = fmaf(a.x, w.x, acc);
        acc = fmaf(a.y, w.y, acc);
        acc = fmaf(a.z, w.z, acc);
        acc = fmaf(a.w, w.w, acc);
    }
    if (j < 16)       Bp[token * DSTATE + j] = acc;
    else if (j < 32)  Cp[token * DSTATE + j - 16] = acc;
    else              dt[token] = acc;
}

// ---------------------------------------------------------------------------
// delta = softplus(dt_raw[token] * W_dt[d] + b_dt[d])
// ---------------------------------------------------------------------------
__global__ void delta_kernel(const float* __restrict__ dt,
                             const float* __restrict__ Wdt,
                             const float* __restrict__ bdt,
                             float* __restrict__ delta) {
    int idx = blockIdx.x * 256 + threadIdx.x;
    int d  = idx & (DINNER - 1);
    int bt = idx >> 11;
    float v = fmaf(dt[bt], Wdt[d], bdt[d]);
    float sp = fmaxf(v, 0.f) + log1pf(__expf(-fabsf(v)));
    delta[idx] = sp;
}

// ---------------------------------------------------------------------------
// Selective scan + skip + SiLU(z) gate.
// Block = 16 channels of one batch; warp = 2 channels x 16 states (lane = state).
// Chunked shared staging of B/C/delta/x/z (T=64).
// ---------------------------------------------------------------------------
__global__ __launch_bounds__(256)
void scan_kernel(const float* __restrict__ A_log,
                 const float* __restrict__ Dskip,
                 const float* __restrict__ delta,
                 const float* __restrict__ xc,
                 const float* __restrict__ Bp,
                 const float* __restrict__ Cp,
                 const float* __restrict__ xz,
                 float* __restrict__ y) {
    int cbase = blockIdx.x * 16;                  // global channel 0..4095
    int b     = cbase >> 11;
    int dbase = cbase & (DINNER - 1);
    int tid  = threadIdx.x;
    int lane = tid & 31;
    int warp = tid >> 5;
    int half = lane >> 4;
    int n    = lane & 15;
    int c_loc = warp * 2 + half;                  // 0..15
    int d = dbase + c_loc;

    float A_n = -__expf(A_log[(size_t)d * DSTATE + n]);
    float Dsk = Dskip[d];
    float h = 0.f;

    __shared__ float sB[64][16];
    __shared__ float sC[64][16];
    __shared__ float sD[64][16];
    __shared__ float sX[64][16];
    __shared__ float sZ[64][16];

    const size_t base_t = (size_t)b * 1024;

    for (int t0 = 0; t0 < 1024; t0 += 64) {
        __syncthreads();
        {   // B / C: contiguous 1024-float copies
            ((float4*)&sB[0][0])[tid] = ((const float4*)(Bp + (base_t + t0) * DSTATE))[tid];
            ((float4*)&sC[0][0])[tid] = ((const float4*)(Cp + (base_t + t0) * DSTATE))[tid];
            // delta / x / z: 64 rows of 16 floats each (strided)
            int tt = tid >> 2;
            int q  = (tid & 3) * 4;
            size_t r = (base_t + t0 + tt);
            *(float4*)&sD[tt][q] = *(const float4*)(delta + r * DINNER + dbase + q);
            *(float4*)&sX[tt][q] = *(const float4*)(xc    + r * DINNER + dbase + q);
            *(float4*)&sZ[tt][q] = *(const float4*)(xz    + r * 2 * DINNER + DINNER + dbase + q);
        }
        __syncthreads();
        #pragma unroll 4
        for (int tt = 0; tt < 64; tt++) {
            float dlt = sD[tt][c_loc];
            float xv  = sX[tt][c_loc];
            float Bv  = sB[tt][n];
            float Cv  = sC[tt][n];
            float a = __expf(dlt * A_n);
            h = fmaf(a, h, dlt * xv * Bv);
            float p = h * Cv;
            p += __shfl_xor_sync(0xffffffffu, p, 1);
            p += __shfl_xor_sync(0xffffffffu, p, 2);
            p += __shfl_xor_sync(0xffffffffu, p, 4);
            p += __shfl_xor_sync(0xffffffffu, p, 8);
            if (n == 0) {
                float zv = sZ[tt][c_loc];
                float g  = zv / (1.f + __expf(-zv));
                y[(base_t + t0 + tt) * DINNER + d] = (p + xv * Dsk) * g;
            }
        }
    }
}

// ---------------------------------------------------------------------------
// Launcher
// ---------------------------------------------------------------------------
extern "C" void kernel_launch(void* const* d_in, const int* in_sizes, int n_in,
                              void* d_out, int out_size) {
    const float* x      = (const float*)d_in[0];
    const float* norm_w = (const float*)d_in[1];
    const float* W_in   = (const float*)d_in[2];
    const float* conv_w = (const float*)d_in[3];
    const float* conv_b = (const float*)d_in[4];
    const float* W_x    = (const float*)d_in[5];
    const float* A_log  = (const float*)d_in[6];
    const float* D_skip = (const float*)d_in[7];
    const float* W_dt   = (const float*)d_in[8];
    const float* b_dt   = (const float*)d_in[9];
    const float* W_out  = (const float*)d_in[10];
    float* out = (float*)d_out;

    float *xn, *xz, *xc, *Bp, *Cp, *dt, *delta, *y;
    cudaGetSymbolAddress((void**)&xn,    g_xn);
    cudaGetSymbolAddress((void**)&xz,    g_xz);
    cudaGetSymbolAddress((void**)&xc,    g_xc);
    cudaGetSymbolAddress((void**)&Bp,    g_Bp);
    cudaGetSymbolAddress((void**)&Cp,    g_Cp);
    cudaGetSymbolAddress((void**)&dt,    g_dt);
    cudaGetSymbolAddress((void**)&delta, g_delta);
    cudaGetSymbolAddress((void**)&y,     g_y);

    // 1. RMSNorm
    rmsnorm_kernel<<<TOKENS, 256>>>(x, norm_w, xn);
    // 2. xz = xn @ W_in^T     (2048 x 4096 x 1024)
    sgemm_tt<<<dim3(2 * DINNER / BN, TOKENS / BM), 256>>>(xn, W_in, xz, nullptr,
                                                          TOKENS, 2 * DINNER, DMODEL);
    // 3. depthwise conv + silu
    conv_silu_kernel<<<TOKENS * DINNER / 256, 256>>>(xz, conv_w, conv_b, xc);
    // 4. B/C/dt projection
    ssm_proj_kernel<<<TOKENS / 8, dim3(33, 8)>>>(xc, W_x, Bp, Cp, dt);
    // 5. delta = softplus(...)
    delta_kernel<<<TOKENS * DINNER / 256, 256>>>(dt, W_dt, b_dt, delta);
    // 6. selective scan + skip + gate
    scan_kernel<<<4096 / 16, 256>>>(A_log, D_skip, delta, xc, Bp, Cp, xz, y);
    // 7. out = y_gated @ W_out^T + residual   (2048 x 1024 x 2048)
    sgemm_tt<<<dim3(DMODEL / BN, TOKENS / BM), 256>>>(y, W_out, out, x,
                                                      TOKENS, DMODEL, DINNER);
}

// round 4
// speedup vs baseline: 1.9757x; 1.9757x over previous
#include <cuda_runtime.h>
#include <cuda_bf16.h>
#include <cstdint>

// ---------------------------------------------------------------------------
// Problem constants (B=2, L=1024, D_MODEL=1024, D_INNER=2048, N=16, CONV=4)
// ---------------------------------------------------------------------------
#define TOKENS   2048
#define DMODEL   1024
#define DINNER   2048
#define DSTATE   16

// ---------------------------------------------------------------------------
// Scratch buffers (static device globals; no allocation allowed)
// ---------------------------------------------------------------------------
__device__ float g_xn   [TOKENS * DMODEL];
__device__ float g_xz   [TOKENS * 2 * DINNER];
__device__ float g_xc   [TOKENS * DINNER];
__device__ float g_Bp   [TOKENS * DSTATE];
__device__ float g_Cp   [TOKENS * DSTATE];
__device__ float g_dt   [TOKENS];
__device__ float g_delta[TOKENS * DINNER];
__device__ float g_y    [TOKENS * DINNER];

// ---------------------------------------------------------------------------
// Helpers
// ---------------------------------------------------------------------------
__device__ __forceinline__ uint32_t smem_u32(const void* p) {
    uint32_t a;
    asm("{ .reg .u64 t; cvta.to.shared.u64 t, %1; cvt.u32.u64 %0, t; }" : "=r"(a) : "l"(p));
    return a;
}
__device__ __forceinline__ uint32_t f2tf32(float f) {
    uint32_t u;
    asm("cvt.rna.tf32.f32 %0, %1;" : "=r"(u) : "f"(f));
    return u;
}
__device__ __forceinline__ void cp_async16(uint32_t saddr, const void* gaddr) {
    asm volatile("cp.async.cg.shared.global [%0], [%1], 16;" :: "r"(saddr), "l"(gaddr));
}
#define CP_COMMIT() asm volatile("cp.async.commit_group;" ::: "memory")
#define CP_WAIT0()  asm volatile("cp.async.wait_group 0;" ::: "memory")

__device__ __forceinline__ void mma_tf32(float* c, const uint32_t* a, const uint32_t* b) {
    asm volatile(
        "mma.sync.aligned.m16n8k8.row.col.f32.tf32.tf32.f32 "
        "{%0,%1,%2,%3}, {%4,%5,%6,%7}, {%8,%9}, {%0,%1,%2,%3};"
        : "+f"(c[0]), "+f"(c[1]), "+f"(c[2]), "+f"(c[3])
        : "r"(a[0]), "r"(a[1]), "r"(a[2]), "r"(a[3]), "r"(b[0]), "r"(b[1]));
}

// ---------------------------------------------------------------------------
// TF32 mma.sync GEMM: C[m][n] = sum_k A[m][k]*B[n][k] (+ Res[m][n])
// Block tile 128x128x32, 256 threads (8 warps, 2x4), warp tile 64x32.
// cp.async double-buffered smem, pitch 36 floats (conflict-free frags).
// ---------------------------------------------------------------------------
#define BM 128
#define BN 128
#define BK 32
#define PITCH 36
#define TILE_F (BM * PITCH)              // floats per tile
#define GSMEM_BYTES (4 * TILE_F * 4)     // A0 A1 B0 B1

__global__ __launch_bounds__(256, 2)
void gemm_mma(const float* __restrict__ A, const float* __restrict__ Bm,
              float* __restrict__ C, const float* __restrict__ Res,
              int M, int N, int K) {
    extern __shared__ float smem[];
    float* sA[2] = { smem,            smem + TILE_F };
    float* sB[2] = { smem + 2*TILE_F, smem + 3*TILE_F };
    const uint32_t sAu[2] = { smem_u32(sA[0]), smem_u32(sA[1]) };
    const uint32_t sBu[2] = { smem_u32(sB[0]), smem_u32(sB[1]) };

    const int tid = threadIdx.x;
    const int lane = tid & 31, wid = tid >> 5;
    const int g = lane >> 2, tg = lane & 3;
    const int wm = wid & 1, wn = wid >> 1;          // warp 64x32 tile
    const int bm = blockIdx.y * BM, bn = blockIdx.x * BN;

    const int lrow = tid >> 3;                      // 0..31
    const int lcol = (tid & 7) * 4;                 // 0..28

    float acc[4][4][4];
    #pragma unroll
    for (int i = 0; i < 4; i++)
        #pragma unroll
        for (int j = 0; j < 4; j++)
            #pragma unroll
            for (int q = 0; q < 4; q++) acc[i][j][q] = 0.f;

    const int nk = K / BK;

    // prologue: load tile 0 into buf 0
    #pragma unroll
    for (int i = 0; i < 4; i++) {
        int r = lrow + i * 32;
        uint32_t so = (uint32_t)(r * PITCH + lcol) * 4u;
        cp_async16(sAu[0] + so, A + (size_t)(bm + r) * K + lcol);
        cp_async16(sBu[0] + so, Bm + (size_t)(bn + r) * K + lcol);
    }
    CP_COMMIT();

    int buf = 0;
    for (int kc = 0; kc < nk; kc++) {
        CP_WAIT0();
        __syncthreads();
        if (kc + 1 < nk) {
            int k0 = (kc + 1) * BK;
            #pragma unroll
            for (int i = 0; i < 4; i++) {
                int r = lrow + i * 32;
                uint32_t so = (uint32_t)(r * PITCH + lcol) * 4u;
                cp_async16(sAu[buf ^ 1] + so, A + (size_t)(bm + r) * K + k0 + lcol);
                cp_async16(sBu[buf ^ 1] + so, Bm + (size_t)(bn + r) * K + k0 + lcol);
            }
            CP_COMMIT();
        }
        const float* As = sA[buf];
        const float* Bs = sB[buf];
        #pragma unroll
        for (int kk = 0; kk < 4; kk++) {
            const int k = kk * 8;
            uint32_t afr[4][4], bfr[4][2];
            #pragma unroll
            for (int mi = 0; mi < 4; mi++) {
                const float* p = As + (wm * 64 + mi * 16) * PITCH + k;
                afr[mi][0] = f2tf32(p[ g      * PITCH + tg]);
                afr[mi][1] = f2tf32(p[(g + 8) * PITCH + tg]);
                afr[mi][2] = f2tf32(p[ g      * PITCH + tg + 4]);
                afr[mi][3] = f2tf32(p[(g + 8) * PITCH + tg + 4]);
            }
            #pragma unroll
            for (int ni = 0; ni < 4; ni++) {
                const float* q = Bs + (wn * 32 + ni * 8 + g) * PITCH + k;
                bfr[ni][0] = f2tf32(q[tg]);
                bfr[ni][1] = f2tf32(q[tg + 4]);
            }
            #pragma unroll
            for (int mi = 0; mi < 4; mi++)
                #pragma unroll
                for (int ni = 0; ni < 4; ni++)
                    mma_tf32(acc[mi][ni], afr[mi], bfr[ni]);
        }
        buf ^= 1;
    }

    // epilogue: c0,c1 -> (row g), c2,c3 -> (row g+8); cols tg*2, tg*2+1
    #pragma unroll
    for (int mi = 0; mi < 4; mi++) {
        #pragma unroll
        for (int ni = 0; ni < 4; ni++) {
            int row0 = bm + wm * 64 + mi * 16 + g;
            int col  = bn + wn * 32 + ni * 8 + tg * 2;
            size_t o0 = (size_t)row0 * N + col;
            size_t o1 = (size_t)(row0 + 8) * N + col;
            float2 v0 = make_float2(acc[mi][ni][0], acc[mi][ni][1]);
            float2 v1 = make_float2(acc[mi][ni][2], acc[mi][ni][3]);
            if (Res) {
                float2 r0 = *(const float2*)(Res + o0);
                float2 r1 = *(const float2*)(Res + o1);
                v0.x += r0.x; v0.y += r0.y;
                v1.x += r1.x; v1.y += r1.y;
            }
            *(float2*)(C + o0) = v0;
            *(float2*)(C + o1) = v1;
        }
    }
}

// ---------------------------------------------------------------------------
// RMSNorm: one block per token
// ---------------------------------------------------------------------------
__global__ void rmsnorm_kernel(const float* __restrict__ x,
                               const float* __restrict__ w,
                               float* __restrict__ out) {
    int t = blockIdx.x;
    const float4* xr = (const float4*)(x + (size_t)t * DMODEL);
    float4 v = xr[threadIdx.x];
    float ss = v.x*v.x + v.y*v.y + v.z*v.z + v.w*v.w;
    #pragma unroll
    for (int o = 16; o > 0; o >>= 1) ss += __shfl_xor_sync(0xffffffffu, ss, o);
    __shared__ float sred[8];
    __shared__ float sinv;
    int lane = threadIdx.x & 31, wid = threadIdx.x >> 5;
    if (lane == 0) sred[wid] = ss;
    __syncthreads();
    if (threadIdx.x == 0) {
        float tot = 0.f;
        #pragma unroll
        for (int i = 0; i < 8; i++) tot += sred[i];
        sinv = rsqrtf(tot * (1.0f / DMODEL) + 1e-6f);
    }
    __syncthreads();
    float inv = sinv;
    float4 wv = ((const float4*)w)[threadIdx.x];
    ((float4*)(out + (size_t)t * DMODEL))[threadIdx.x] =
        make_float4(v.x*inv*wv.x, v.y*inv*wv.y, v.z*inv*wv.z, v.w*inv*wv.w);
}

// ---------------------------------------------------------------------------
// Depthwise causal conv (width 4) + bias + SiLU
// ---------------------------------------------------------------------------
__global__ void conv_silu_kernel(const float* __restrict__ xz,
                                 const float* __restrict__ convw,
                                 const float* __restrict__ convb,
                                 float* __restrict__ xc) {
    int idx = blockIdx.x * 256 + threadIdx.x;
    int d  = idx & (DINNER - 1);
    int bt = idx >> 11;
    int t  = bt & 1023;
    float4 w = *(const float4*)(convw + (size_t)d * 4);
    size_t base = (size_t)bt * (2 * DINNER) + d;
    float acc = convb[d];
    if (t >= 3) {
        acc = fmaf(xz[base - 3 * 2 * DINNER], w.x, acc);
        acc = fmaf(xz[base - 2 * 2 * DINNER], w.y, acc);
        acc = fmaf(xz[base - 1 * 2 * DINNER], w.z, acc);
        acc = fmaf(xz[base],                  w.w, acc);
    } else {
        float wj[4] = {w.x, w.y, w.z, w.w};
        #pragma unroll
        for (int j = 0; j < 4; j++) {
            int tt = t - 3 + j;
            if (tt >= 0) acc = fmaf(xz[base + (size_t)(j - 3) * 2 * DINNER], wj[j], acc);
        }
    }
    xc[idx] = acc / (1.f + __expf(-acc));
}

// ---------------------------------------------------------------------------
// ssm projection: smem-staged skinny GEMM (2048 x 33 x 2048).
// Block (33,8)=264 thr, 16 tokens/block, 2 tokens/thread, K chunks of 128.
// ---------------------------------------------------------------------------
__global__ __launch_bounds__(264)
void ssm_proj2(const float* __restrict__ xc, const float* __restrict__ Wx,
               float* __restrict__ Bp, float* __restrict__ Cp,
               float* __restrict__ dt) {
    __shared__ float sW[33 * 132];
    __shared__ float sX[16 * 132];
    int j = threadIdx.x, gy = threadIdx.y;
    int tid = j + 33 * gy;
    int tokbase = blockIdx.x * 16;
    int t0 = gy * 2, t1 = gy * 2 + 1;
    float acc0 = 0.f, acc1 = 0.f;

    for (int k0 = 0; k0 < DINNER; k0 += 128) {
        __syncthreads();
        {   // W chunk: 33 rows x 128
            int row = tid >> 3, l8 = tid & 7;
            const float4* src = (const float4*)(Wx + (size_t)row * DINNER + k0);
            float4* dst = (float4*)(sW + row * 132);
            #pragma unroll
            for (int q = 0; q < 4; q++) dst[q * 8 + l8] = src[q * 8 + l8];
        }
        if (tid < 256) {  // X chunk: 16 rows x 128
            int row = tid >> 4, l16 = tid & 15;
            const float4* src = (const float4*)(xc + (size_t)(tokbase + row) * DINNER + k0);
            float4* dst = (float4*)(sX + row * 132);
            dst[l16] = src[l16];
            dst[16 + l16] = src[16 + l16];
        }
        __syncthreads();
        const float4* wr = (const float4*)(sW + j * 132);
        const float4* x0 = (const float4*)(sX + t0 * 132);
        const float4* x1 = (const float4*)(sX + t1 * 132);
        #pragma unroll 8
        for (int k4 = 0; k4 < 32; k4++) {
            float4 w = wr[k4], a = x0[k4], b = x1[k4];
            acc0 = fmaf(w.x, a.x, acc0); acc0 = fmaf(w.y, a.y, acc0);
            acc0 = fmaf(w.z, a.z, acc0); acc0 = fmaf(w.w, a.w, acc0);
            acc1 = fmaf(w.x, b.x, acc1); acc1 = fmaf(w.y, b.y, acc1);
            acc1 = fmaf(w.z, b.z, acc1); acc1 = fmaf(w.w, b.w, acc1);
        }
    }
    int tok0 = tokbase + t0, tok1 = tokbase + t1;
    if (j < 16)      { Bp[tok0 * DSTATE + j] = acc0;      Bp[tok1 * DSTATE + j] = acc1; }
    else if (j < 32) { Cp[tok0 * DSTATE + j - 16] = acc0; Cp[tok1 * DSTATE + j - 16] = acc1; }
    else             { dt[tok0] = acc0;                   dt[tok1] = acc1; }
}

// ---------------------------------------------------------------------------
// delta = softplus(dt_raw[token] * W_dt[d] + b_dt[d])
// ---------------------------------------------------------------------------
__global__ void delta_kernel(const float* __restrict__ dt,
                             const float* __restrict__ Wdt,
                             const float* __restrict__ bdt,
                             float* __restrict__ delta) {
    int idx = blockIdx.x * 256 + threadIdx.x;
    int d  = idx & (DINNER - 1);
    int bt = idx >> 11;
    float v = fmaf(dt[bt], Wdt[d], bdt[d]);
    delta[idx] = fmaxf(v, 0.f) + log1pf(__expf(-fabsf(v)));
}

// ---------------------------------------------------------------------------
// Selective scan + skip + SiLU(z) gate (lane = state, 2 channels per warp)
// ---------------------------------------------------------------------------
__global__ __launch_bounds__(256)
void scan_kernel(const float* __restrict__ A_log,
                 const float* __restrict__ Dskip,
                 const float* __restrict__ delta,
                 const float* __restrict__ xc,
                 const float* __restrict__ Bp,
                 const float* __restrict__ Cp,
                 const float* __restrict__ xz,
                 float* __restrict__ y) {
    int cbase = blockIdx.x * 16;
    int b     = cbase >> 11;
    int dbase = cbase & (DINNER - 1);
    int tid  = threadIdx.x;
    int lane = tid & 31;
    int warp = tid >> 5;
    int half = lane >> 4;
    int n    = lane & 15;
    int c_loc = warp * 2 + half;
    int d = dbase + c_loc;

    float A_n = -__expf(A_log[(size_t)d * DSTATE + n]);
    float Dsk = Dskip[d];
    float h = 0.f;

    __shared__ float sB[64][16];
    __shared__ float sC[64][16];
    __shared__ float sD[64][16];
    __shared__ float sX[64][16];
    __shared__ float sZ[64][16];

    const size_t base_t = (size_t)b * 1024;

    for (int t0 = 0; t0 < 1024; t0 += 64) {
        __syncthreads();
        {
            ((float4*)&sB[0][0])[tid] = ((const float4*)(Bp + (base_t + t0) * DSTATE))[tid];
            ((float4*)&sC[0][0])[tid] = ((const float4*)(Cp + (base_t + t0) * DSTATE))[tid];
            int tt = tid >> 2;
            int q  = (tid & 3) * 4;
            size_t r = (base_t + t0 + tt);
            *(float4*)&sD[tt][q] = *(const float4*)(delta + r * DINNER + dbase + q);
            *(float4*)&sX[tt][q] = *(const float4*)(xc    + r * DINNER + dbase + q);
            *(float4*)&sZ[tt][q] = *(const float4*)(xz    + r * 2 * DINNER + DINNER + dbase + q);
        }
        __syncthreads();
        #pragma unroll 4
        for (int tt = 0; tt < 64; tt++) {
            float dlt = sD[tt][c_loc];
            float xv  = sX[tt][c_loc];
            float a = __expf(dlt * A_n);
            h = fmaf(a, h, dlt * xv * sB[tt][n]);
            float p = h * sC[tt][n];
            p += __shfl_xor_sync(0xffffffffu, p, 1);
            p += __shfl_xor_sync(0xffffffffu, p, 2);
            p += __shfl_xor_sync(0xffffffffu, p, 4);
            p += __shfl_xor_sync(0xffffffffu, p, 8);
            if (n == 0) {
                float zv = sZ[tt][c_loc];
                float gate = zv / (1.f + __expf(-zv));
                y[(base_t + t0 + tt) * DINNER + d] = (p + xv * Dsk) * gate;
            }
        }
    }
}

// ---------------------------------------------------------------------------
// Launcher
// ---------------------------------------------------------------------------
extern "C" void kernel_launch(void* const* d_in, const int* in_sizes, int n_in,
                              void* d_out, int out_size) {
    const float* x      = (const float*)d_in[0];
    const float* norm_w = (const float*)d_in[1];
    const float* W_in   = (const float*)d_in[2];
    const float* conv_w = (const float*)d_in[3];
    const float* conv_b = (const float*)d_in[4];
    const float* W_x    = (const float*)d_in[5];
    const float* A_log  = (const float*)d_in[6];
    const float* D_skip = (const float*)d_in[7];
    const float* W_dt   = (const float*)d_in[8];
    const float* b_dt   = (const float*)d_in[9];
    const float* W_out  = (const float*)d_in[10];
    float* out = (float*)d_out;

    float *xn, *xz, *xc, *Bp, *Cp, *dt, *delta, *y;
    cudaGetSymbolAddress((void**)&xn,    g_xn);
    cudaGetSymbolAddress((void**)&xz,    g_xz);
    cudaGetSymbolAddress((void**)&xc,    g_xc);
    cudaGetSymbolAddress((void**)&Bp,    g_Bp);
    cudaGetSymbolAddress((void**)&Cp,    g_Cp);
    cudaGetSymbolAddress((void**)&dt,    g_dt);
    cudaGetSymbolAddress((void**)&delta, g_delta);
    cudaGetSymbolAddress((void**)&y,     g_y);

    cudaFuncSetAttribute(gemm_mma, cudaFuncAttributeMaxDynamicSharedMemorySize, GSMEM_BYTES);

    // 1. RMSNorm
    rmsnorm_kernel<<<TOKENS, 256>>>(x, norm_w, xn);
    // 2. xz = xn @ W_in^T   (M=2048, N=4096, K=1024)  tf32 mma.sync
    gemm_mma<<<dim3(4096 / BN, 2048 / BM), 256, GSMEM_BYTES>>>(
        xn, W_in, xz, nullptr, TOKENS, 2 * DINNER, DMODEL);
    // 3. depthwise conv + silu
    conv_silu_kernel<<<TOKENS * DINNER / 256, 256>>>(xz, conv_w, conv_b, xc);
    // 4. B/C/dt projection (smem-staged)
    ssm_proj2<<<TOKENS / 16, dim3(33, 8)>>>(xc, W_x, Bp, Cp, dt);
    // 5. delta = softplus(...)
    delta_kernel<<<TOKENS * DINNER / 256, 256>>>(dt, W_dt, b_dt, delta);
    // 6. selective scan + skip + gate
    scan_kernel<<<4096 / 16, 256>>>(A_log, D_skip, delta, xc, Bp, Cp, xz, y);
    // 7. out = y_gated @ W_out^T + residual  (M=2048, N=1024, K=2048) tf32 mma.sync
    gemm_mma<<<dim3(1024 / BN, 2048 / BM), 256, GSMEM_BYTES>>>(
        y, W_out, out, x, TOKENS, DMODEL, DINNER);
}

// round 5
// speedup vs baseline: 2.1061x; 1.0660x over previous
#include <cuda_runtime.h>
#include <cuda_bf16.h>
#include <cstdint>

// ---------------------------------------------------------------------------
// Problem constants (B=2, L=1024, D_MODEL=1024, D_INNER=2048, N=16, CONV=4)
// ---------------------------------------------------------------------------
#define TOKENS   2048
#define DMODEL   1024
#define DINNER   2048
#define DSTATE   16

// ---------------------------------------------------------------------------
// Scratch buffers (static device globals; no allocation allowed)
// ---------------------------------------------------------------------------
__device__ float g_xn   [TOKENS * DMODEL];         // tf32-rounded rmsnorm out
__device__ float g_xz   [TOKENS * 2 * DINNER];
__device__ float g_xc   [TOKENS * DINNER];
__device__ float g_Bp   [TOKENS * DSTATE];
__device__ float g_Cp   [TOKENS * DSTATE];
__device__ float g_dt   [TOKENS];
__device__ float g_y    [TOKENS * DINNER];         // tf32-rounded gated scan out
__device__ float g_WinT [2 * DINNER * DMODEL];     // tf32-rounded W_in
__device__ float g_WoutT[DMODEL * DINNER];         // tf32-rounded W_out

// ---------------------------------------------------------------------------
// Helpers
// ---------------------------------------------------------------------------
__device__ __forceinline__ uint32_t smem_u32(const void* p) {
    uint32_t a;
    asm("{ .reg .u64 t; cvta.to.shared.u64 t, %1; cvt.u32.u64 %0, t; }" : "=r"(a) : "l"(p));
    return a;
}
__device__ __forceinline__ float f2tf32f(float f) {
    uint32_t u;
    asm("cvt.rna.tf32.f32 %0, %1;" : "=r"(u) : "f"(f));
    return __uint_as_float(u);
}
__device__ __forceinline__ void cp_async16(uint32_t saddr, const void* gaddr) {
    asm volatile("cp.async.cg.shared.global [%0], [%1], 16;" :: "r"(saddr), "l"(gaddr));
}
#define CP_COMMIT() asm volatile("cp.async.commit_group;" ::: "memory")
#define CP_WAIT0()  asm volatile("cp.async.wait_group 0;" ::: "memory")

__device__ __forceinline__ void mma_tf32(float* c, const uint32_t* a, const uint32_t* b) {
    asm volatile(
        "mma.sync.aligned.m16n8k8.row.col.f32.tf32.tf32.f32 "
        "{%0,%1,%2,%3}, {%4,%5,%6,%7}, {%8,%9}, {%0,%1,%2,%3};"
        : "+f"(c[0]), "+f"(c[1]), "+f"(c[2]), "+f"(c[3])
        : "r"(a[0]), "r"(a[1]), "r"(a[2]), "r"(a[3]), "r"(b[0]), "r"(b[1]));
}

// ---------------------------------------------------------------------------
// One-pass tf32 rounding of W_in (4M floats) and W_out (2M floats)
// ---------------------------------------------------------------------------
#define WIN_F4  (2 * DINNER * DMODEL / 4)   // 1048576
#define WOUT_F4 (DMODEL * DINNER / 4)       // 524288
__global__ void round_w_kernel(const float* __restrict__ Win, float* __restrict__ WinT,
                               const float* __restrict__ Wout, float* __restrict__ WoutT) {
    int i = blockIdx.x * 256 + threadIdx.x;
    if (i < WIN_F4) {
        float4 v = ((const float4*)Win)[i];
        ((float4*)WinT)[i] = make_float4(f2tf32f(v.x), f2tf32f(v.y), f2tf32f(v.z), f2tf32f(v.w));
    } else {
        int j = i - WIN_F4;
        float4 v = ((const float4*)Wout)[j];
        ((float4*)WoutT)[j] = make_float4(f2tf32f(v.x), f2tf32f(v.y), f2tf32f(v.z), f2tf32f(v.w));
    }
}

// ---------------------------------------------------------------------------
// TF32 mma.sync GEMM (inputs pre-rounded to tf32 values; no cvt in loop)
// Block tile 128x128x32, 256 threads (8 warps, 2x4), warp tile 64x32.
// ---------------------------------------------------------------------------
#define BM 128
#define BN 128
#define BK 32
#define PITCH 36
#define TILE_F (BM * PITCH)
#define GSMEM_BYTES (4 * TILE_F * 4)

__global__ __launch_bounds__(256, 2)
void gemm_mma(const float* __restrict__ A, const float* __restrict__ Bm,
              float* __restrict__ C, const float* __restrict__ Res,
              int M, int N, int K) {
    extern __shared__ float smem[];
    float* sA[2] = { smem,            smem + TILE_F };
    float* sB[2] = { smem + 2*TILE_F, smem + 3*TILE_F };
    const uint32_t sAu[2] = { smem_u32(sA[0]), smem_u32(sA[1]) };
    const uint32_t sBu[2] = { smem_u32(sB[0]), smem_u32(sB[1]) };

    const int tid = threadIdx.x;
    const int lane = tid & 31, wid = tid >> 5;
    const int g = lane >> 2, tg = lane & 3;
    const int wm = wid & 1, wn = wid >> 1;
    const int bm = blockIdx.y * BM, bn = blockIdx.x * BN;

    const int lrow = tid >> 3;
    const int lcol = (tid & 7) * 4;

    float acc[4][4][4];
    #pragma unroll
    for (int i = 0; i < 4; i++)
        #pragma unroll
        for (int j = 0; j < 4; j++)
            #pragma unroll
            for (int q = 0; q < 4; q++) acc[i][j][q] = 0.f;

    const int nk = K / BK;

    #pragma unroll
    for (int i = 0; i < 4; i++) {
        int r = lrow + i * 32;
        uint32_t so = (uint32_t)(r * PITCH + lcol) * 4u;
        cp_async16(sAu[0] + so, A + (size_t)(bm + r) * K + lcol);
        cp_async16(sBu[0] + so, Bm + (size_t)(bn + r) * K + lcol);
    }
    CP_COMMIT();

    int buf = 0;
    for (int kc = 0; kc < nk; kc++) {
        CP_WAIT0();
        __syncthreads();
        if (kc + 1 < nk) {
            int k0 = (kc + 1) * BK;
            #pragma unroll
            for (int i = 0; i < 4; i++) {
                int r = lrow + i * 32;
                uint32_t so = (uint32_t)(r * PITCH + lcol) * 4u;
                cp_async16(sAu[buf ^ 1] + so, A + (size_t)(bm + r) * K + k0 + lcol);
                cp_async16(sBu[buf ^ 1] + so, Bm + (size_t)(bn + r) * K + k0 + lcol);
            }
            CP_COMMIT();
        }
        const uint32_t* As = (const uint32_t*)sA[buf];
        const uint32_t* Bs = (const uint32_t*)sB[buf];
        #pragma unroll
        for (int kk = 0; kk < 4; kk++) {
            const int k = kk * 8;
            uint32_t afr[4][4], bfr[4][2];
            #pragma unroll
            for (int mi = 0; mi < 4; mi++) {
                const uint32_t* p = As + (wm * 64 + mi * 16) * PITCH + k;
                afr[mi][0] = p[ g      * PITCH + tg];
                afr[mi][1] = p[(g + 8) * PITCH + tg];
                afr[mi][2] = p[ g      * PITCH + tg + 4];
                afr[mi][3] = p[(g + 8) * PITCH + tg + 4];
            }
            #pragma unroll
            for (int ni = 0; ni < 4; ni++) {
                const uint32_t* q = Bs + (wn * 32 + ni * 8 + g) * PITCH + k;
                bfr[ni][0] = q[tg];
                bfr[ni][1] = q[tg + 4];
            }
            #pragma unroll
            for (int mi = 0; mi < 4; mi++)
                #pragma unroll
                for (int ni = 0; ni < 4; ni++)
                    mma_tf32(acc[mi][ni], afr[mi], bfr[ni]);
        }
        buf ^= 1;
    }

    #pragma unroll
    for (int mi = 0; mi < 4; mi++) {
        #pragma unroll
        for (int ni = 0; ni < 4; ni++) {
            int row0 = bm + wm * 64 + mi * 16 + g;
            int col  = bn + wn * 32 + ni * 8 + tg * 2;
            size_t o0 = (size_t)row0 * N + col;
            size_t o1 = (size_t)(row0 + 8) * N + col;
            float2 v0 = make_float2(acc[mi][ni][0], acc[mi][ni][1]);
            float2 v1 = make_float2(acc[mi][ni][2], acc[mi][ni][3]);
            if (Res) {
                float2 r0 = *(const float2*)(Res + o0);
                float2 r1 = *(const float2*)(Res + o1);
                v0.x += r0.x; v0.y += r0.y;
                v1.x += r1.x; v1.y += r1.y;
            }
            *(float2*)(C + o0) = v0;
            *(float2*)(C + o1) = v1;
        }
    }
}

// ---------------------------------------------------------------------------
// RMSNorm: one block per token; output pre-rounded to tf32 (feeds GEMM1 only)
// ---------------------------------------------------------------------------
__global__ void rmsnorm_kernel(const float* __restrict__ x,
                               const float* __restrict__ w,
                               float* __restrict__ out) {
    int t = blockIdx.x;
    const float4* xr = (const float4*)(x + (size_t)t * DMODEL);
    float4 v = xr[threadIdx.x];
    float ss = v.x*v.x + v.y*v.y + v.z*v.z + v.w*v.w;
    #pragma unroll
    for (int o = 16; o > 0; o >>= 1) ss += __shfl_xor_sync(0xffffffffu, ss, o);
    __shared__ float sred[8];
    __shared__ float sinv;
    int lane = threadIdx.x & 31, wid = threadIdx.x >> 5;
    if (lane == 0) sred[wid] = ss;
    __syncthreads();
    if (threadIdx.x == 0) {
        float tot = 0.f;
        #pragma unroll
        for (int i = 0; i < 8; i++) tot += sred[i];
        sinv = rsqrtf(tot * (1.0f / DMODEL) + 1e-6f);
    }
    __syncthreads();
    float inv = sinv;
    float4 wv = ((const float4*)w)[threadIdx.x];
    ((float4*)(out + (size_t)t * DMODEL))[threadIdx.x] =
        make_float4(f2tf32f(v.x*inv*wv.x), f2tf32f(v.y*inv*wv.y),
                    f2tf32f(v.z*inv*wv.z), f2tf32f(v.w*inv*wv.w));
}

// ---------------------------------------------------------------------------
// Depthwise causal conv (width 4) + bias + SiLU
// ---------------------------------------------------------------------------
__global__ void conv_silu_kernel(const float* __restrict__ xz,
                                 const float* __restrict__ convw,
                                 const float* __restrict__ convb,
                                 float* __restrict__ xc) {
    int idx = blockIdx.x * 256 + threadIdx.x;
    int d  = idx & (DINNER - 1);
    int bt = idx >> 11;
    int t  = bt & 1023;
    float4 w = *(const float4*)(convw + (size_t)d * 4);
    size_t base = (size_t)bt * (2 * DINNER) + d;
    float acc = convb[d];
    if (t >= 3) {
        acc = fmaf(xz[base - 3 * 2 * DINNER], w.x, acc);
        acc = fmaf(xz[base - 2 * 2 * DINNER], w.y, acc);
        acc = fmaf(xz[base - 1 * 2 * DINNER], w.z, acc);
        acc = fmaf(xz[base],                  w.w, acc);
    } else {
        float wj[4] = {w.x, w.y, w.z, w.w};
        #pragma unroll
        for (int j = 0; j < 4; j++) {
            int tt = t - 3 + j;
            if (tt >= 0) acc = fmaf(xz[base + (size_t)(j - 3) * 2 * DINNER], wj[j], acc);
        }
    }
    xc[idx] = acc / (1.f + __expf(-acc));
}

// ---------------------------------------------------------------------------
// ssm projection, split-K x4 with atomicAdd epilogue (outputs pre-zeroed).
// Block (33,8)=264 thr, 16 tokens/block, K range 512 per block (4 x 128).
// ---------------------------------------------------------------------------
#define KSPLIT 4
#define KRANGE (DINNER / KSPLIT)     // 512
__global__ __launch_bounds__(264)
void ssm_proj3(const float* __restrict__ xc, const float* __restrict__ Wx,
               float* __restrict__ Bp, float* __restrict__ Cp,
               float* __restrict__ dt) {
    __shared__ float sW[33 * 132];
    __shared__ float sX[16 * 132];
    int j = threadIdx.x, gy = threadIdx.y;
    int tid = j + 33 * gy;
    int tokbase = blockIdx.x * 16;
    int kbase = blockIdx.y * KRANGE;
    int t0 = gy * 2, t1 = gy * 2 + 1;
    float acc0 = 0.f, acc1 = 0.f;

    for (int kq = 0; kq < KRANGE; kq += 128) {
        int k0 = kbase + kq;
        __syncthreads();
        {   // W chunk: 33 rows x 128
            int row = tid >> 3, l8 = tid & 7;
            const float4* src = (const float4*)(Wx + (size_t)row * DINNER + k0);
            float4* dst = (float4*)(sW + row * 132);
            #pragma unroll
            for (int q = 0; q < 4; q++) dst[q * 8 + l8] = src[q * 8 + l8];
        }
        if (tid < 256) {  // X chunk: 16 rows x 128
            int row = tid >> 4, l16 = tid & 15;
            const float4* src = (const float4*)(xc + (size_t)(tokbase + row) * DINNER + k0);
            float4* dst = (float4*)(sX + row * 132);
            dst[l16] = src[l16];
            dst[16 + l16] = src[16 + l16];
        }
        __syncthreads();
        const float4* wr = (const float4*)(sW + j * 132);
        const float4* x0 = (const float4*)(sX + t0 * 132);
        const float4* x1 = (const float4*)(sX + t1 * 132);
        #pragma unroll 8
        for (int k4 = 0; k4 < 32; k4++) {
            float4 w = wr[k4], a = x0[k4], b = x1[k4];
            acc0 = fmaf(w.x, a.x, acc0); acc0 = fmaf(w.y, a.y, acc0);
            acc0 = fmaf(w.z, a.z, acc0); acc0 = fmaf(w.w, a.w, acc0);
            acc1 = fmaf(w.x, b.x, acc1); acc1 = fmaf(w.y, b.y, acc1);
            acc1 = fmaf(w.z, b.z, acc1); acc1 = fmaf(w.w, b.w, acc1);
        }
    }
    int tok0 = tokbase + t0, tok1 = tokbase + t1;
    if (j < 16)      { atomicAdd(&Bp[tok0 * DSTATE + j], acc0);
                       atomicAdd(&Bp[tok1 * DSTATE + j], acc1); }
    else if (j < 32) { atomicAdd(&Cp[tok0 * DSTATE + j - 16], acc0);
                       atomicAdd(&Cp[tok1 * DSTATE + j - 16], acc1); }
    else             { atomicAdd(&dt[tok0], acc0);
                       atomicAdd(&dt[tok1], acc1); }
}

// ---------------------------------------------------------------------------
// Selective scan + fused softplus(delta) + skip + SiLU(z) gate.
// Lane = state, 2 channels per warp. y output pre-rounded to tf32.
// ---------------------------------------------------------------------------
__global__ __launch_bounds__(256)
void scan_kernel(const float* __restrict__ A_log,
                 const float* __restrict__ Dskip,
                 const float* __restrict__ dtv,
                 const float* __restrict__ Wdt,
                 const float* __restrict__ bdt,
                 const float* __restrict__ xc,
                 const float* __restrict__ Bp,
                 const float* __restrict__ Cp,
                 const float* __restrict__ xz,
                 float* __restrict__ y) {
    int cbase = blockIdx.x * 16;
    int b     = cbase >> 11;
    int dbase = cbase & (DINNER - 1);
    int tid  = threadIdx.x;
    int lane = tid & 31;
    int warp = tid >> 5;
    int half = lane >> 4;
    int n    = lane & 15;
    int c_loc = warp * 2 + half;
    int d = dbase + c_loc;

    float A_n = -__expf(A_log[(size_t)d * DSTATE + n]);
    float Dsk = Dskip[d];
    float h = 0.f;

    // per-thread delta params for the sD fill (c = tid & 15 fixed across j)
    int cfill = tid & 15;
    float wdt_c = Wdt[dbase + cfill];
    float bdt_c = bdt[dbase + cfill];

    __shared__ float sB[64][16];
    __shared__ float sC[64][16];
    __shared__ float sD[64][16];
    __shared__ float sX[64][16];
    __shared__ float sZ[64][16];

    const size_t base_t = (size_t)b * 1024;

    for (int t0 = 0; t0 < 1024; t0 += 64) {
        __syncthreads();
        {
            ((float4*)&sB[0][0])[tid] = ((const float4*)(Bp + (base_t + t0) * DSTATE))[tid];
            ((float4*)&sC[0][0])[tid] = ((const float4*)(Cp + (base_t + t0) * DSTATE))[tid];
            int tt = tid >> 2;
            int q  = (tid & 3) * 4;
            size_t r = (base_t + t0 + tt);
            *(float4*)&sX[tt][q] = *(const float4*)(xc + r * DINNER + dbase + q);
            *(float4*)&sZ[tt][q] = *(const float4*)(xz + r * 2 * DINNER + DINNER + dbase + q);
            // fused delta: 4 entries per thread, column fixed = cfill
            #pragma unroll
            for (int jj = 0; jj < 4; jj++) {
                int tf = jj * 16 + (tid >> 4);
                float v = fmaf(__ldg(dtv + base_t + t0 + tf), wdt_c, bdt_c);
                sD[tf][cfill] = fmaxf(v, 0.f) + log1pf(__expf(-fabsf(v)));
            }
        }
        __syncthreads();
        #pragma unroll 4
        for (int tt = 0; tt < 64; tt++) {
            float dlt = sD[tt][c_loc];
            float xv  = sX[tt][c_loc];
            float a = __expf(dlt * A_n);
            h = fmaf(a, h, dlt * xv * sB[tt][n]);
            float p = h * sC[tt][n];
            p += __shfl_xor_sync(0xffffffffu, p, 1);
            p += __shfl_xor_sync(0xffffffffu, p, 2);
            p += __shfl_xor_sync(0xffffffffu, p, 4);
            p += __shfl_xor_sync(0xffffffffu, p, 8);
            if (n == 0) {
                float zv = sZ[tt][c_loc];
                float gate = zv / (1.f + __expf(-zv));
                y[(base_t + t0 + tt) * DINNER + d] = f2tf32f((p + xv * Dsk) * gate);
            }
        }
    }
}

// ---------------------------------------------------------------------------
// Launcher
// ---------------------------------------------------------------------------
extern "C" void kernel_launch(void* const* d_in, const int* in_sizes, int n_in,
                              void* d_out, int out_size) {
    const float* x      = (const float*)d_in[0];
    const float* norm_w = (const float*)d_in[1];
    const float* W_in   = (const float*)d_in[2];
    const float* conv_w = (const float*)d_in[3];
    const float* conv_b = (const float*)d_in[4];
    const float* W_x    = (const float*)d_in[5];
    const float* A_log  = (const float*)d_in[6];
    const float* D_skip = (const float*)d_in[7];
    const float* W_dt   = (const float*)d_in[8];
    const float* b_dt   = (const float*)d_in[9];
    const float* W_out  = (const float*)d_in[10];
    float* out = (float*)d_out;

    float *xn, *xz, *xc, *Bp, *Cp, *dt, *y, *WinT, *WoutT;
    cudaGetSymbolAddress((void**)&xn,    g_xn);
    cudaGetSymbolAddress((void**)&xz,    g_xz);
    cudaGetSymbolAddress((void**)&xc,    g_xc);
    cudaGetSymbolAddress((void**)&Bp,    g_Bp);
    cudaGetSymbolAddress((void**)&Cp,    g_Cp);
    cudaGetSymbolAddress((void**)&dt,    g_dt);
    cudaGetSymbolAddress((void**)&y,     g_y);
    cudaGetSymbolAddress((void**)&WinT,  g_WinT);
    cudaGetSymbolAddress((void**)&WoutT, g_WoutT);

    cudaFuncSetAttribute(gemm_mma, cudaFuncAttributeMaxDynamicSharedMemorySize, GSMEM_BYTES);

    // 0. round weights to tf32 values (once per launch)
    round_w_kernel<<<(WIN_F4 + WOUT_F4) / 256, 256>>>(W_in, WinT, W_out, WoutT);
    // zero split-K accumulators
    cudaMemsetAsync(Bp, 0, TOKENS * DSTATE * sizeof(float));
    cudaMemsetAsync(Cp, 0, TOKENS * DSTATE * sizeof(float));
    cudaMemsetAsync(dt, 0, TOKENS * sizeof(float));
    // 1. RMSNorm (tf32-rounded output)
    rmsnorm_kernel<<<TOKENS, 256>>>(x, norm_w, xn);
    // 2. xz = xn @ W_in^T   (M=2048, N=4096, K=1024)
    gemm_mma<<<dim3(4096 / BN, 2048 / BM), 256, GSMEM_BYTES>>>(
        xn, WinT, xz, nullptr, TOKENS, 2 * DINNER, DMODEL);
    // 3. depthwise conv + silu
    conv_silu_kernel<<<TOKENS * DINNER / 256, 256>>>(xz, conv_w, conv_b, xc);
    // 4. B/C/dt projection (split-K x4, atomic reduce)
    ssm_proj3<<<dim3(TOKENS / 16, KSPLIT), dim3(33, 8)>>>(xc, W_x, Bp, Cp, dt);
    // 5. selective scan + fused delta + skip + gate (tf32-rounded y)
    scan_kernel<<<4096 / 16, 256>>>(A_log, D_skip, dt, W_dt, b_dt, xc, Bp, Cp, xz, y);
    // 6. out = y_gated @ W_out^T + residual  (M=2048, N=1024, K=2048)
    gemm_mma<<<dim3(1024 / BN, 2048 / BM), 256, GSMEM_BYTES>>>(
        y, WoutT, out, x, TOKENS, DMODEL, DINNER);
}

// round 6
// speedup vs baseline: 2.3270x; 1.1049x over previous
#include <cuda_runtime.h>
#include <cuda_bf16.h>
#include <cstdint>

// ---------------------------------------------------------------------------
// Problem constants (B=2, L=1024, D_MODEL=1024, D_INNER=2048, N=16, CONV=4)
// ---------------------------------------------------------------------------
#define TOKENS   2048
#define DMODEL   1024
#define DINNER   2048
#define DSTATE   16

// ---------------------------------------------------------------------------
// Scratch buffers (static device globals; no allocation allowed)
// ---------------------------------------------------------------------------
__device__ float g_xn   [TOKENS * DMODEL];         // tf32-rounded rmsnorm out
__device__ float g_xz   [TOKENS * 2 * DINNER];
__device__ float g_xc   [TOKENS * DINNER];
__device__ float g_Bp   [TOKENS * DSTATE];
__device__ float g_Cp   [TOKENS * DSTATE];
__device__ float g_dt   [TOKENS];
__device__ float g_y    [TOKENS * DINNER];         // tf32-rounded gated scan out
__device__ float g_WinT [2 * DINNER * DMODEL];     // tf32-rounded W_in
__device__ float g_WoutT[DMODEL * DINNER];         // tf32-rounded W_out

// ---------------------------------------------------------------------------
// Helpers
// ---------------------------------------------------------------------------
__device__ __forceinline__ uint32_t smem_u32(const void* p) {
    uint32_t a;
    asm("{ .reg .u64 t; cvta.to.shared.u64 t, %1; cvt.u32.u64 %0, t; }" : "=r"(a) : "l"(p));
    return a;
}
__device__ __forceinline__ float f2tf32f(float f) {
    uint32_t u;
    asm("cvt.rna.tf32.f32 %0, %1;" : "=r"(u) : "f"(f));
    return __uint_as_float(u);
}
__device__ __forceinline__ void cp_async16(uint32_t saddr, const void* gaddr) {
    asm volatile("cp.async.cg.shared.global [%0], [%1], 16;" :: "r"(saddr), "l"(gaddr));
}
#define CP_COMMIT() asm volatile("cp.async.commit_group;" ::: "memory")
#define CP_WAIT1()  asm volatile("cp.async.wait_group 1;" ::: "memory")

__device__ __forceinline__ void mma_tf32(float* c, const uint32_t* a, const uint32_t* b) {
    asm volatile(
        "mma.sync.aligned.m16n8k8.row.col.f32.tf32.tf32.f32 "
        "{%0,%1,%2,%3}, {%4,%5,%6,%7}, {%8,%9}, {%0,%1,%2,%3};"
        : "+f"(c[0]), "+f"(c[1]), "+f"(c[2]), "+f"(c[3])
        : "r"(a[0]), "r"(a[1]), "r"(a[2]), "r"(a[3]), "r"(b[0]), "r"(b[1]));
}
__device__ __forceinline__ void ldsm_x4(uint32_t* r, uint32_t addr) {
    asm volatile("ldmatrix.sync.aligned.m8n8.x4.shared.b16 {%0,%1,%2,%3}, [%4];"
        : "=r"(r[0]), "=r"(r[1]), "=r"(r[2]), "=r"(r[3]) : "r"(addr));
}
__device__ __forceinline__ void ldsm_x2(uint32_t* r, uint32_t addr) {
    asm volatile("ldmatrix.sync.aligned.m8n8.x2.shared.b16 {%0,%1}, [%2];"
        : "=r"(r[0]), "=r"(r[1]) : "r"(addr));
}
__device__ __forceinline__ void red_add_f32(float* p, float v) {
    asm volatile("red.global.add.f32 [%0], %1;" :: "l"(p), "f"(v) : "memory");
}

// ---------------------------------------------------------------------------
// One-pass tf32 rounding of W_in (4M floats) and W_out (2M floats)
// ---------------------------------------------------------------------------
#define WIN_F4  (2 * DINNER * DMODEL / 4)
#define WOUT_F4 (DMODEL * DINNER / 4)
__global__ void round_w_kernel(const float* __restrict__ Win, float* __restrict__ WinT,
                               const float* __restrict__ Wout, float* __restrict__ WoutT) {
    int i = blockIdx.x * 256 + threadIdx.x;
    if (i < WIN_F4) {
        float4 v = ((const float4*)Win)[i];
        ((float4*)WinT)[i] = make_float4(f2tf32f(v.x), f2tf32f(v.y), f2tf32f(v.z), f2tf32f(v.w));
    } else {
        int j = i - WIN_F4;
        float4 v = ((const float4*)Wout)[j];
        ((float4*)WoutT)[j] = make_float4(f2tf32f(v.x), f2tf32f(v.y), f2tf32f(v.z), f2tf32f(v.w));
    }
}

// ---------------------------------------------------------------------------
// TF32 mma.sync GEMM, 3-stage cp.async pipeline, ldmatrix fragment loads.
// Block tile 128x128x32, 256 threads (8 warps, 2x4), warp tile 64x32.
// ATOMIC=1: split-K over blockIdx.z, epilogue red.global.add (C pre-seeded).
// ---------------------------------------------------------------------------
#define BM 128
#define BN 128
#define BK 32
#define PITCH 36
#define TILE_F (BM * PITCH)
#define NSTAGE 3
#define GSMEM_BYTES (2 * NSTAGE * TILE_F * 4)    // 110592 B

template<int ATOMIC>
__global__ __launch_bounds__(256, 2)
void gemm_mma(const float* __restrict__ A, const float* __restrict__ Bm,
              float* __restrict__ C, const float* __restrict__ Res,
              int M, int N, int K) {
    extern __shared__ float smem[];
    uint32_t sAu[NSTAGE], sBu[NSTAGE];
    #pragma unroll
    for (int s = 0; s < NSTAGE; s++) {
        sAu[s] = smem_u32(smem + 2 * s * TILE_F);
        sBu[s] = smem_u32(smem + (2 * s + 1) * TILE_F);
    }

    const int tid = threadIdx.x;
    const int lane = tid & 31, wid = tid >> 5;
    const int g = lane >> 2, tg = lane & 3;
    const int wm = wid & 1, wn = wid >> 1;
    const int bm = blockIdx.y * BM, bn = blockIdx.x * BN;

    const int kseg  = K / gridDim.z;
    const int kbase = blockIdx.z * kseg;
    const int nk    = kseg / BK;

    const int lrow = tid >> 3;
    const int lcol = (tid & 7) * 4;

    // per-lane ldmatrix offsets (in floats)
    const int aoff = (wm * 64 + (lane & 15)) * PITCH + (lane >> 4) * 4;
    const int boff = (wn * 32 + (lane & 7)) * PITCH + ((lane >> 3) & 1) * 4;

    float acc[4][4][4];
    #pragma unroll
    for (int i = 0; i < 4; i++)
        #pragma unroll
        for (int j = 0; j < 4; j++)
            #pragma unroll
            for (int q = 0; q < 4; q++) acc[i][j][q] = 0.f;

    // prologue: stages 0, 1
    #pragma unroll
    for (int s = 0; s < 2; s++) {
        int k0 = kbase + s * BK;
        #pragma unroll
        for (int i = 0; i < 4; i++) {
            int r = lrow + i * 32;
            uint32_t so = (uint32_t)(r * PITCH + lcol) * 4u;
            cp_async16(sAu[s] + so, A + (size_t)(bm + r) * K + k0 + lcol);
            cp_async16(sBu[s] + so, Bm + (size_t)(bn + r) * K + k0 + lcol);
        }
        CP_COMMIT();
    }

    int buf = 0, nbuf = 2;
    for (int kc = 0; kc < nk; kc++) {
        CP_WAIT1();
        __syncthreads();
        if (kc + 2 < nk) {
            int k0 = kbase + (kc + 2) * BK;
            #pragma unroll
            for (int i = 0; i < 4; i++) {
                int r = lrow + i * 32;
                uint32_t so = (uint32_t)(r * PITCH + lcol) * 4u;
                cp_async16(sAu[nbuf] + so, A + (size_t)(bm + r) * K + k0 + lcol);
                cp_async16(sBu[nbuf] + so, Bm + (size_t)(bn + r) * K + k0 + lcol);
            }
            CP_COMMIT();
        }
        const uint32_t sa = sAu[buf], sb = sBu[buf];
        #pragma unroll
        for (int kk = 0; kk < 4; kk++) {
            uint32_t afr[4][4], bfr[4][2];
            #pragma unroll
            for (int mi = 0; mi < 4; mi++)
                ldsm_x4(afr[mi], sa + (uint32_t)(aoff + mi * 16 * PITCH + kk * 8) * 4u);
            #pragma unroll
            for (int ni = 0; ni < 4; ni++)
                ldsm_x2(bfr[ni], sb + (uint32_t)(boff + ni * 8 * PITCH + kk * 8) * 4u);
            #pragma unroll
            for (int mi = 0; mi < 4; mi++)
                #pragma unroll
                for (int ni = 0; ni < 4; ni++)
                    mma_tf32(acc[mi][ni], afr[mi], bfr[ni]);
        }
        buf = (buf + 1) % NSTAGE;
        nbuf = (nbuf + 1) % NSTAGE;
    }

    #pragma unroll
    for (int mi = 0; mi < 4; mi++) {
        #pragma unroll
        for (int ni = 0; ni < 4; ni++) {
            int row0 = bm + wm * 64 + mi * 16 + g;
            int col  = bn + wn * 32 + ni * 8 + tg * 2;
            size_t o0 = (size_t)row0 * N + col;
            size_t o1 = (size_t)(row0 + 8) * N + col;
            if (ATOMIC) {
                red_add_f32(C + o0,     acc[mi][ni][0]);
                red_add_f32(C + o0 + 1, acc[mi][ni][1]);
                red_add_f32(C + o1,     acc[mi][ni][2]);
                red_add_f32(C + o1 + 1, acc[mi][ni][3]);
            } else {
                float2 v0 = make_float2(acc[mi][ni][0], acc[mi][ni][1]);
                float2 v1 = make_float2(acc[mi][ni][2], acc[mi][ni][3]);
                if (Res) {
                    float2 r0 = *(const float2*)(Res + o0);
                    float2 r1 = *(const float2*)(Res + o1);
                    v0.x += r0.x; v0.y += r0.y;
                    v1.x += r1.x; v1.y += r1.y;
                }
                *(float2*)(C + o0) = v0;
                *(float2*)(C + o1) = v1;
            }
        }
    }
}

// ---------------------------------------------------------------------------
// RMSNorm: one block per token; output pre-rounded to tf32 (feeds GEMM1 only)
// ---------------------------------------------------------------------------
__global__ void rmsnorm_kernel(const float* __restrict__ x,
                               const float* __restrict__ w,
                               float* __restrict__ out) {
    int t = blockIdx.x;
    const float4* xr = (const float4*)(x + (size_t)t * DMODEL);
    float4 v = xr[threadIdx.x];
    float ss = v.x*v.x + v.y*v.y + v.z*v.z + v.w*v.w;
    #pragma unroll
    for (int o = 16; o > 0; o >>= 1) ss += __shfl_xor_sync(0xffffffffu, ss, o);
    __shared__ float sred[8];
    __shared__ float sinv;
    int lane = threadIdx.x & 31, wid = threadIdx.x >> 5;
    if (lane == 0) sred[wid] = ss;
    __syncthreads();
    if (threadIdx.x == 0) {
        float tot = 0.f;
        #pragma unroll
        for (int i = 0; i < 8; i++) tot += sred[i];
        sinv = rsqrtf(tot * (1.0f / DMODEL) + 1e-6f);
    }
    __syncthreads();
    float inv = sinv;
    float4 wv = ((const float4*)w)[threadIdx.x];
    ((float4*)(out + (size_t)t * DMODEL))[threadIdx.x] =
        make_float4(f2tf32f(v.x*inv*wv.x), f2tf32f(v.y*inv*wv.y),
                    f2tf32f(v.z*inv*wv.z), f2tf32f(v.w*inv*wv.w));
}

// ---------------------------------------------------------------------------
// Depthwise causal conv (width 4) + bias + SiLU
// ---------------------------------------------------------------------------
__global__ void conv_silu_kernel(const float* __restrict__ xz,
                                 const float* __restrict__ convw,
                                 const float* __restrict__ convb,
                                 float* __restrict__ xc) {
    int idx = blockIdx.x * 256 + threadIdx.x;
    int d  = idx & (DINNER - 1);
    int bt = idx >> 11;
    int t  = bt & 1023;
    float4 w = *(const float4*)(convw + (size_t)d * 4);
    size_t base = (size_t)bt * (2 * DINNER) + d;
    float acc = convb[d];
    if (t >= 3) {
        acc = fmaf(xz[base - 3 * 2 * DINNER], w.x, acc);
        acc = fmaf(xz[base - 2 * 2 * DINNER], w.y, acc);
        acc = fmaf(xz[base - 1 * 2 * DINNER], w.z, acc);
        acc = fmaf(xz[base],                  w.w, acc);
    } else {
        float wj[4] = {w.x, w.y, w.z, w.w};
        #pragma unroll
        for (int j = 0; j < 4; j++) {
            int tt = t - 3 + j;
            if (tt >= 0) acc = fmaf(xz[base + (size_t)(j - 3) * 2 * DINNER], wj[j], acc);
        }
    }
    xc[idx] = acc / (1.f + __expf(-acc));
}

// ---------------------------------------------------------------------------
// ssm projection, split-K x4 with atomicAdd epilogue (outputs pre-zeroed).
// ---------------------------------------------------------------------------
#define KSPLIT 4
#define KRANGE (DINNER / KSPLIT)
__global__ __launch_bounds__(264)
void ssm_proj3(const float* __restrict__ xc, const float* __restrict__ Wx,
               float* __restrict__ Bp, float* __restrict__ Cp,
               float* __restrict__ dt) {
    __shared__ float sW[33 * 132];
    __shared__ float sX[16 * 132];
    int j = threadIdx.x, gy = threadIdx.y;
    int tid = j + 33 * gy;
    int tokbase = blockIdx.x * 16;
    int kbase = blockIdx.y * KRANGE;
    int t0 = gy * 2, t1 = gy * 2 + 1;
    float acc0 = 0.f, acc1 = 0.f;

    for (int kq = 0; kq < KRANGE; kq += 128) {
        int k0 = kbase + kq;
        __syncthreads();
        {
            int row = tid >> 3, l8 = tid & 7;
            const float4* src = (const float4*)(Wx + (size_t)row * DINNER + k0);
            float4* dst = (float4*)(sW + row * 132);
            #pragma unroll
            for (int q = 0; q < 4; q++) dst[q * 8 + l8] = src[q * 8 + l8];
        }
        if (tid < 256) {
            int row = tid >> 4, l16 = tid & 15;
            const float4* src = (const float4*)(xc + (size_t)(tokbase + row) * DINNER + k0);
            float4* dst = (float4*)(sX + row * 132);
            dst[l16] = src[l16];
            dst[16 + l16] = src[16 + l16];
        }
        __syncthreads();
        const float4* wr = (const float4*)(sW + j * 132);
        const float4* x0 = (const float4*)(sX + t0 * 132);
        const float4* x1 = (const float4*)(sX + t1 * 132);
        #pragma unroll 8
        for (int k4 = 0; k4 < 32; k4++) {
            float4 w = wr[k4], a = x0[k4], b = x1[k4];
            acc0 = fmaf(w.x, a.x, acc0); acc0 = fmaf(w.y, a.y, acc0);
            acc0 = fmaf(w.z, a.z, acc0); acc0 = fmaf(w.w, a.w, acc0);
            acc1 = fmaf(w.x, b.x, acc1); acc1 = fmaf(w.y, b.y, acc1);
            acc1 = fmaf(w.z, b.z, acc1); acc1 = fmaf(w.w, b.w, acc1);
        }
    }
    int tok0 = tokbase + t0, tok1 = tokbase + t1;
    if (j < 16)      { atomicAdd(&Bp[tok0 * DSTATE + j], acc0);
                       atomicAdd(&Bp[tok1 * DSTATE + j], acc1); }
    else if (j < 32) { atomicAdd(&Cp[tok0 * DSTATE + j - 16], acc0);
                       atomicAdd(&Cp[tok1 * DSTATE + j - 16], acc1); }
    else             { atomicAdd(&dt[tok0], acc0);
                       atomicAdd(&dt[tok1], acc1); }
}

// ---------------------------------------------------------------------------
// Selective scan + fused softplus(delta) + skip + SiLU(z) gate.
// ---------------------------------------------------------------------------
__global__ __launch_bounds__(256)
void scan_kernel(const float* __restrict__ A_log,
                 const float* __restrict__ Dskip,
                 const float* __restrict__ dtv,
                 const float* __restrict__ Wdt,
                 const float* __restrict__ bdt,
                 const float* __restrict__ xc,
                 const float* __restrict__ Bp,
                 const float* __restrict__ Cp,
                 const float* __restrict__ xz,
                 float* __restrict__ y) {
    int cbase = blockIdx.x * 16;
    int b     = cbase >> 11;
    int dbase = cbase & (DINNER - 1);
    int tid  = threadIdx.x;
    int lane = tid & 31;
    int warp = tid >> 5;
    int half = lane >> 4;
    int n    = lane & 15;
    int c_loc = warp * 2 + half;
    int d = dbase + c_loc;

    float A_n = -__expf(A_log[(size_t)d * DSTATE + n]);
    float Dsk = Dskip[d];
    float h = 0.f;

    int cfill = tid & 15;
    float wdt_c = Wdt[dbase + cfill];
    float bdt_c = bdt[dbase + cfill];

    __shared__ float sB[64][16];
    __shared__ float sC[64][16];
    __shared__ float sD[64][16];
    __shared__ float sX[64][16];
    __shared__ float sZ[64][16];

    const size_t base_t = (size_t)b * 1024;

    for (int t0 = 0; t0 < 1024; t0 += 64) {
        __syncthreads();
        {
            ((float4*)&sB[0][0])[tid] = ((const float4*)(Bp + (base_t + t0) * DSTATE))[tid];
            ((float4*)&sC[0][0])[tid] = ((const float4*)(Cp + (base_t + t0) * DSTATE))[tid];
            int tt = tid >> 2;
            int q  = (tid & 3) * 4;
            size_t r = (base_t + t0 + tt);
            *(float4*)&sX[tt][q] = *(const float4*)(xc + r * DINNER + dbase + q);
            *(float4*)&sZ[tt][q] = *(const float4*)(xz + r * 2 * DINNER + DINNER + dbase + q);
            #pragma unroll
            for (int jj = 0; jj < 4; jj++) {
                int tf = jj * 16 + (tid >> 4);
                float v = fmaf(__ldg(dtv + base_t + t0 + tf), wdt_c, bdt_c);
                sD[tf][cfill] = fmaxf(v, 0.f) + log1pf(__expf(-fabsf(v)));
            }
        }
        __syncthreads();
        #pragma unroll 4
        for (int tt = 0; tt < 64; tt++) {
            float dlt = sD[tt][c_loc];
            float xv  = sX[tt][c_loc];
            float a = __expf(dlt * A_n);
            h = fmaf(a, h, dlt * xv * sB[tt][n]);
            float p = h * sC[tt][n];
            p += __shfl_xor_sync(0xffffffffu, p, 1);
            p += __shfl_xor_sync(0xffffffffu, p, 2);
            p += __shfl_xor_sync(0xffffffffu, p, 4);
            p += __shfl_xor_sync(0xffffffffu, p, 8);
            if (n == 0) {
                float zv = sZ[tt][c_loc];
                float gate = zv / (1.f + __expf(-zv));
                y[(base_t + t0 + tt) * DINNER + d] = f2tf32f((p + xv * Dsk) * gate);
            }
        }
    }
}

// ---------------------------------------------------------------------------
// Launcher
// ---------------------------------------------------------------------------
extern "C" void kernel_launch(void* const* d_in, const int* in_sizes, int n_in,
                              void* d_out, int out_size) {
    const float* x      = (const float*)d_in[0];
    const float* norm_w = (const float*)d_in[1];
    const float* W_in   = (const float*)d_in[2];
    const float* conv_w = (const float*)d_in[3];
    const float* conv_b = (const float*)d_in[4];
    const float* W_x    = (const float*)d_in[5];
    const float* A_log  = (const float*)d_in[6];
    const float* D_skip = (const float*)d_in[7];
    const float* W_dt   = (const float*)d_in[8];
    const float* b_dt   = (const float*)d_in[9];
    const float* W_out  = (const float*)d_in[10];
    float* out = (float*)d_out;

    float *xn, *xz, *xc, *Bp, *Cp, *dt, *y, *WinT, *WoutT;
    cudaGetSymbolAddress((void**)&xn,    g_xn);
    cudaGetSymbolAddress((void**)&xz,    g_xz);
    cudaGetSymbolAddress((void**)&xc,    g_xc);
    cudaGetSymbolAddress((void**)&Bp,    g_Bp);
    cudaGetSymbolAddress((void**)&Cp,    g_Cp);
    cudaGetSymbolAddress((void**)&dt,    g_dt);
    cudaGetSymbolAddress((void**)&y,     g_y);
    cudaGetSymbolAddress((void**)&WinT,  g_WinT);
    cudaGetSymbolAddress((void**)&WoutT, g_WoutT);

    cudaFuncSetAttribute(gemm_mma<0>, cudaFuncAttributeMaxDynamicSharedMemorySize, GSMEM_BYTES);
    cudaFuncSetAttribute(gemm_mma<1>, cudaFuncAttributeMaxDynamicSharedMemorySize, GSMEM_BYTES);

    // 0. round weights to tf32 values; zero split-K accumulators; seed out=residual
    round_w_kernel<<<(WIN_F4 + WOUT_F4) / 256, 256>>>(W_in, WinT, W_out, WoutT);
    cudaMemsetAsync(Bp, 0, TOKENS * DSTATE * sizeof(float));
    cudaMemsetAsync(Cp, 0, TOKENS * DSTATE * sizeof(float));
    cudaMemsetAsync(dt, 0, TOKENS * sizeof(float));
    cudaMemcpyAsync(out, x, (size_t)TOKENS * DMODEL * sizeof(float),
                    cudaMemcpyDeviceToDevice);
    // 1. RMSNorm (tf32-rounded output)
    rmsnorm_kernel<<<TOKENS, 256>>>(x, norm_w, xn);
    // 2. xz = xn @ W_in^T   (M=2048, N=4096, K=1024)
    gemm_mma<0><<<dim3(4096 / BN, 2048 / BM, 1), 256, GSMEM_BYTES>>>(
        xn, WinT, xz, nullptr, TOKENS, 2 * DINNER, DMODEL);
    // 3. depthwise conv + silu
    conv_silu_kernel<<<TOKENS * DINNER / 256, 256>>>(xz, conv_w, conv_b, xc);
    // 4. B/C/dt projection (split-K x4, atomic reduce)
    ssm_proj3<<<dim3(TOKENS / 16, KSPLIT), dim3(33, 8)>>>(xc, W_x, Bp, Cp, dt);
    // 5. selective scan + fused delta + skip + gate (tf32-rounded y)
    scan_kernel<<<4096 / 16, 256>>>(A_log, D_skip, dt, W_dt, b_dt, xc, Bp, Cp, xz, y);
    // 6. out += y_gated @ W_out^T  (split-K x2, red.global; out pre-seeded with x)
    gemm_mma<1><<<dim3(1024 / BN, 2048 / BM, 2), 256, GSMEM_BYTES>>>(
        y, WoutT, out, nullptr, TOKENS, DMODEL, DINNER);
}

// round 7
// speedup vs baseline: 2.5007x; 1.0746x over previous
#include <cuda_runtime.h>
#include <cuda_fp16.h>
#include <cuda_bf16.h>
#include <cstdint>

// ---------------------------------------------------------------------------
// Problem constants (B=2, L=1024, D_MODEL=1024, D_INNER=2048, N=16, CONV=4)
// ---------------------------------------------------------------------------
#define TOKENS   2048
#define DMODEL   1024
#define DINNER   2048
#define DSTATE   16

// ---------------------------------------------------------------------------
// Scratch buffers (static device globals; no allocation allowed)
// ---------------------------------------------------------------------------
__device__ __half g_xnh [TOKENS * DMODEL];         // fp16 rmsnorm out
__device__ __half g_WinH[2 * DINNER * DMODEL];     // fp16 W_in
__device__ float  g_xz  [TOKENS * 2 * DINNER];
__device__ float  g_xc  [TOKENS * DINNER];
__device__ float  g_Bp  [TOKENS * DSTATE];
__device__ float  g_Cp  [TOKENS * DSTATE];
__device__ float  g_dt  [TOKENS];
__device__ float  g_y   [TOKENS * DINNER];         // tf32-rounded gated scan out
__device__ float  g_WoutT[DMODEL * DINNER];        // tf32-rounded W_out

// ---------------------------------------------------------------------------
// Helpers
// ---------------------------------------------------------------------------
__device__ __forceinline__ uint32_t smem_u32(const void* p) {
    uint32_t a;
    asm("{ .reg .u64 t; cvta.to.shared.u64 t, %1; cvt.u32.u64 %0, t; }" : "=r"(a) : "l"(p));
    return a;
}
__device__ __forceinline__ float f2tf32f(float f) {
    uint32_t u;
    asm("cvt.rna.tf32.f32 %0, %1;" : "=r"(u) : "f"(f));
    return __uint_as_float(u);
}
__device__ __forceinline__ void cp_async16(uint32_t saddr, const void* gaddr) {
    asm volatile("cp.async.cg.shared.global [%0], [%1], 16;" :: "r"(saddr), "l"(gaddr));
}
#define CP_COMMIT() asm volatile("cp.async.commit_group;" ::: "memory")
#define CP_WAIT1()  asm volatile("cp.async.wait_group 1;" ::: "memory")

__device__ __forceinline__ void mma_tf32(float* c, const uint32_t* a, const uint32_t* b) {
    asm volatile(
        "mma.sync.aligned.m16n8k8.row.col.f32.tf32.tf32.f32 "
        "{%0,%1,%2,%3}, {%4,%5,%6,%7}, {%8,%9}, {%0,%1,%2,%3};"
        : "+f"(c[0]), "+f"(c[1]), "+f"(c[2]), "+f"(c[3])
        : "r"(a[0]), "r"(a[1]), "r"(a[2]), "r"(a[3]), "r"(b[0]), "r"(b[1]));
}
__device__ __forceinline__ void mma_f16(float* c, const uint32_t* a, const uint32_t* b) {
    asm volatile(
        "mma.sync.aligned.m16n8k16.row.col.f32.f16.f16.f32 "
        "{%0,%1,%2,%3}, {%4,%5,%6,%7}, {%8,%9}, {%0,%1,%2,%3};"
        : "+f"(c[0]), "+f"(c[1]), "+f"(c[2]), "+f"(c[3])
        : "r"(a[0]), "r"(a[1]), "r"(a[2]), "r"(a[3]), "r"(b[0]), "r"(b[1]));
}
__device__ __forceinline__ void ldsm_x4(uint32_t* r, uint32_t addr) {
    asm volatile("ldmatrix.sync.aligned.m8n8.x4.shared.b16 {%0,%1,%2,%3}, [%4];"
        : "=r"(r[0]), "=r"(r[1]), "=r"(r[2]), "=r"(r[3]) : "r"(addr));
}
__device__ __forceinline__ void ldsm_x2(uint32_t* r, uint32_t addr) {
    asm volatile("ldmatrix.sync.aligned.m8n8.x2.shared.b16 {%0,%1}, [%2];"
        : "=r"(r[0]), "=r"(r[1]) : "r"(addr));
}
__device__ __forceinline__ void red_add_f32(float* p, float v) {
    asm volatile("red.global.add.f32 [%0], %1;" :: "l"(p), "f"(v) : "memory");
}

// ---------------------------------------------------------------------------
// One-pass weight conversion: W_in -> fp16, W_out -> tf32-rounded f32
// ---------------------------------------------------------------------------
#define WIN_F4  (2 * DINNER * DMODEL / 4)   // 1048576
#define WOUT_F4 (DMODEL * DINNER / 4)       // 524288
__global__ void round_w_kernel(const float* __restrict__ Win, __half* __restrict__ WinH,
                               const float* __restrict__ Wout, float* __restrict__ WoutT) {
    int i = blockIdx.x * 256 + threadIdx.x;
    if (i < WIN_F4) {
        float4 v = ((const float4*)Win)[i];
        __half2* dst = (__half2*)(WinH + (size_t)i * 4);
        dst[0] = __floats2half2_rn(v.x, v.y);
        dst[1] = __floats2half2_rn(v.z, v.w);
    } else {
        int j = i - WIN_F4;
        float4 v = ((const float4*)Wout)[j];
        ((float4*)WoutT)[j] = make_float4(f2tf32f(v.x), f2tf32f(v.y), f2tf32f(v.z), f2tf32f(v.w));
    }
}

// ---------------------------------------------------------------------------
// FP16 mma.sync GEMM (GEMM1): C[m][n] = sum_k A[m][k]*B[n][k], fp32 accum.
// Block 128x128x32, 256 threads (8 warps 2x4), warp tile 64x32.
// 3-stage cp.async, ldmatrix fragments. PITCH 40 halfs (80 B rows: 16B-aligned,
// 20-bank stride -> 8 rows hit distinct banks).
// ---------------------------------------------------------------------------
#define HBK 32
#define HPITCH 40
#define HTILE (128 * HPITCH)                 // halfs per tile
#define HSMEM_BYTES (2 * 3 * HTILE * 2)      // 61440 B

__global__ __launch_bounds__(256, 2)
void gemm_fp16(const __half* __restrict__ A, const __half* __restrict__ Bm,
               float* __restrict__ C, int M, int N, int K) {
    extern __shared__ __half hsmem[];
    uint32_t sAu[3], sBu[3];
    #pragma unroll
    for (int s = 0; s < 3; s++) {
        sAu[s] = smem_u32(hsmem + 2 * s * HTILE);
        sBu[s] = smem_u32(hsmem + (2 * s + 1) * HTILE);
    }

    const int tid = threadIdx.x;
    const int lane = tid & 31, wid = tid >> 5;
    const int g = lane >> 2, tg = lane & 3;
    const int wm = wid & 1, wn = wid >> 1;
    const int bm = blockIdx.y * 128, bn = blockIdx.x * 128;

    const int lrow = tid >> 1;               // 0..127
    const int hcol = (tid & 1) * 16;         // 0 or 16 halfs

    // ldmatrix per-lane offsets (halfs)
    const int aoff = (wm * 64 + (lane & 15)) * HPITCH + (lane >> 4) * 8;
    const int boff = (wn * 32 + (lane & 7)) * HPITCH + ((lane >> 3) & 1) * 8;

    float acc[4][4][4];
    #pragma unroll
    for (int i = 0; i < 4; i++)
        #pragma unroll
        for (int j = 0; j < 4; j++)
            #pragma unroll
            for (int q = 0; q < 4; q++) acc[i][j][q] = 0.f;

    const int nk = K / HBK;

    #pragma unroll
    for (int s = 0; s < 2; s++) {
        int k0 = s * HBK;
        uint32_t so = (uint32_t)(lrow * HPITCH + hcol) * 2u;
        const __half* ga = A + (size_t)(bm + lrow) * K + k0 + hcol;
        const __half* gb = Bm + (size_t)(bn + lrow) * K + k0 + hcol;
        cp_async16(sAu[s] + so,      ga);
        cp_async16(sAu[s] + so + 16, ga + 8);
        cp_async16(sBu[s] + so,      gb);
        cp_async16(sBu[s] + so + 16, gb + 8);
        CP_COMMIT();
    }

    int buf = 0, nbuf = 2;
    for (int kc = 0; kc < nk; kc++) {
        CP_WAIT1();
        __syncthreads();
        if (kc + 2 < nk) {
            int k0 = (kc + 2) * HBK;
            uint32_t so = (uint32_t)(lrow * HPITCH + hcol) * 2u;
            const __half* ga = A + (size_t)(bm + lrow) * K + k0 + hcol;
            const __half* gb = Bm + (size_t)(bn + lrow) * K + k0 + hcol;
            cp_async16(sAu[nbuf] + so,      ga);
            cp_async16(sAu[nbuf] + so + 16, ga + 8);
            cp_async16(sBu[nbuf] + so,      gb);
            cp_async16(sBu[nbuf] + so + 16, gb + 8);
            CP_COMMIT();
        }
        const uint32_t sa = sAu[buf], sb = sBu[buf];
        #pragma unroll
        for (int kk = 0; kk < 2; kk++) {           // two k16 steps
            uint32_t afr[4][4], bfr[4][2];
            #pragma unroll
            for (int mi = 0; mi < 4; mi++)
                ldsm_x4(afr[mi], sa + (uint32_t)(aoff + mi * 16 * HPITCH + kk * 16) * 2u);
            #pragma unroll
            for (int ni = 0; ni < 4; ni++)
                ldsm_x2(bfr[ni], sb + (uint32_t)(boff + ni * 8 * HPITCH + kk * 16) * 2u);
            #pragma unroll
            for (int mi = 0; mi < 4; mi++)
                #pragma unroll
                for (int ni = 0; ni < 4; ni++)
                    mma_f16(acc[mi][ni], afr[mi], bfr[ni]);
        }
        buf = (buf + 1) % 3;
        nbuf = (nbuf + 1) % 3;
    }

    #pragma unroll
    for (int mi = 0; mi < 4; mi++) {
        #pragma unroll
        for (int ni = 0; ni < 4; ni++) {
            int row0 = bm + wm * 64 + mi * 16 + g;
            int col  = bn + wn * 32 + ni * 8 + tg * 2;
            size_t o0 = (size_t)row0 * N + col;
            size_t o1 = (size_t)(row0 + 8) * N + col;
            *(float2*)(C + o0) = make_float2(acc[mi][ni][0], acc[mi][ni][1]);
            *(float2*)(C + o1) = make_float2(acc[mi][ni][2], acc[mi][ni][3]);
        }
    }
}

// ---------------------------------------------------------------------------
// TF32 mma.sync GEMM (GEMM2), 3-stage cp.async + ldmatrix, split-K atomic.
// ---------------------------------------------------------------------------
#define BM 128
#define BN 128
#define BK 32
#define PITCH 36
#define TILE_F (BM * PITCH)
#define GSMEM_BYTES (2 * 3 * TILE_F * 4)

__global__ __launch_bounds__(256, 2)
void gemm_tf32k(const float* __restrict__ A, const float* __restrict__ Bm,
                float* __restrict__ C, int M, int N, int K) {
    extern __shared__ float smem[];
    uint32_t sAu[3], sBu[3];
    #pragma unroll
    for (int s = 0; s < 3; s++) {
        sAu[s] = smem_u32(smem + 2 * s * TILE_F);
        sBu[s] = smem_u32(smem + (2 * s + 1) * TILE_F);
    }

    const int tid = threadIdx.x;
    const int lane = tid & 31, wid = tid >> 5;
    const int g = lane >> 2, tg = lane & 3;
    const int wm = wid & 1, wn = wid >> 1;
    const int bm = blockIdx.y * BM, bn = blockIdx.x * BN;

    const int kseg  = K / gridDim.z;
    const int kbase = blockIdx.z * kseg;
    const int nk    = kseg / BK;

    const int lrow = tid >> 3;
    const int lcol = (tid & 7) * 4;

    const int aoff = (wm * 64 + (lane & 15)) * PITCH + (lane >> 4) * 4;
    const int boff = (wn * 32 + (lane & 7)) * PITCH + ((lane >> 3) & 1) * 4;

    float acc[4][4][4];
    #pragma unroll
    for (int i = 0; i < 4; i++)
        #pragma unroll
        for (int j = 0; j < 4; j++)
            #pragma unroll
            for (int q = 0; q < 4; q++) acc[i][j][q] = 0.f;

    #pragma unroll
    for (int s = 0; s < 2; s++) {
        int k0 = kbase + s * BK;
        #pragma unroll
        for (int i = 0; i < 4; i++) {
            int r = lrow + i * 32;
            uint32_t so = (uint32_t)(r * PITCH + lcol) * 4u;
            cp_async16(sAu[s] + so, A + (size_t)(bm + r) * K + k0 + lcol);
            cp_async16(sBu[s] + so, Bm + (size_t)(bn + r) * K + k0 + lcol);
        }
        CP_COMMIT();
    }

    int buf = 0, nbuf = 2;
    for (int kc = 0; kc < nk; kc++) {
        CP_WAIT1();
        __syncthreads();
        if (kc + 2 < nk) {
            int k0 = kbase + (kc + 2) * BK;
            #pragma unroll
            for (int i = 0; i < 4; i++) {
                int r = lrow + i * 32;
                uint32_t so = (uint32_t)(r * PITCH + lcol) * 4u;
                cp_async16(sAu[nbuf] + so, A + (size_t)(bm + r) * K + k0 + lcol);
                cp_async16(sBu[nbuf] + so, Bm + (size_t)(bn + r) * K + k0 + lcol);
            }
            CP_COMMIT();
        }
        const uint32_t sa = sAu[buf], sb = sBu[buf];
        #pragma unroll
        for (int kk = 0; kk < 4; kk++) {
            uint32_t afr[4][4], bfr[4][2];
            #pragma unroll
            for (int mi = 0; mi < 4; mi++)
                ldsm_x4(afr[mi], sa + (uint32_t)(aoff + mi * 16 * PITCH + kk * 8) * 4u);
            #pragma unroll
            for (int ni = 0; ni < 4; ni++)
                ldsm_x2(bfr[ni], sb + (uint32_t)(boff + ni * 8 * PITCH + kk * 8) * 4u);
            #pragma unroll
            for (int mi = 0; mi < 4; mi++)
                #pragma unroll
                for (int ni = 0; ni < 4; ni++)
                    mma_tf32(acc[mi][ni], afr[mi], bfr[ni]);
        }
        buf = (buf + 1) % 3;
        nbuf = (nbuf + 1) % 3;
    }

    #pragma unroll
    for (int mi = 0; mi < 4; mi++) {
        #pragma unroll
        for (int ni = 0; ni < 4; ni++) {
            int row0 = bm + wm * 64 + mi * 16 + g;
            int col  = bn + wn * 32 + ni * 8 + tg * 2;
            size_t o0 = (size_t)row0 * N + col;
            size_t o1 = (size_t)(row0 + 8) * N + col;
            red_add_f32(C + o0,     acc[mi][ni][0]);
            red_add_f32(C + o0 + 1, acc[mi][ni][1]);
            red_add_f32(C + o1,     acc[mi][ni][2]);
            red_add_f32(C + o1 + 1, acc[mi][ni][3]);
        }
    }
}

// ---------------------------------------------------------------------------
// RMSNorm: one block per token; fp16 output (feeds GEMM1 only)
// ---------------------------------------------------------------------------
__global__ void rmsnorm_kernel(const float* __restrict__ x,
                               const float* __restrict__ w,
                               __half* __restrict__ out) {
    int t = blockIdx.x;
    const float4* xr = (const float4*)(x + (size_t)t * DMODEL);
    float4 v = xr[threadIdx.x];
    float ss = v.x*v.x + v.y*v.y + v.z*v.z + v.w*v.w;
    #pragma unroll
    for (int o = 16; o > 0; o >>= 1) ss += __shfl_xor_sync(0xffffffffu, ss, o);
    __shared__ float sred[8];
    __shared__ float sinv;
    int lane = threadIdx.x & 31, wid = threadIdx.x >> 5;
    if (lane == 0) sred[wid] = ss;
    __syncthreads();
    if (threadIdx.x == 0) {
        float tot = 0.f;
        #pragma unroll
        for (int i = 0; i < 8; i++) tot += sred[i];
        sinv = rsqrtf(tot * (1.0f / DMODEL) + 1e-6f);
    }
    __syncthreads();
    float inv = sinv;
    float4 wv = ((const float4*)w)[threadIdx.x];
    __half2* dst = (__half2*)(out + (size_t)t * DMODEL + threadIdx.x * 4);
    dst[0] = __floats2half2_rn(v.x*inv*wv.x, v.y*inv*wv.y);
    dst[1] = __floats2half2_rn(v.z*inv*wv.z, v.w*inv*wv.w);
}

// ---------------------------------------------------------------------------
// Depthwise causal conv (width 4) + bias + SiLU
// ---------------------------------------------------------------------------
__global__ void conv_silu_kernel(const float* __restrict__ xz,
                                 const float* __restrict__ convw,
                                 const float* __restrict__ convb,
                                 float* __restrict__ xc) {
    int idx = blockIdx.x * 256 + threadIdx.x;
    int d  = idx & (DINNER - 1);
    int bt = idx >> 11;
    int t  = bt & 1023;
    float4 w = *(const float4*)(convw + (size_t)d * 4);
    size_t base = (size_t)bt * (2 * DINNER) + d;
    float acc = convb[d];
    if (t >= 3) {
        acc = fmaf(xz[base - 3 * 2 * DINNER], w.x, acc);
        acc = fmaf(xz[base - 2 * 2 * DINNER], w.y, acc);
        acc = fmaf(xz[base - 1 * 2 * DINNER], w.z, acc);
        acc = fmaf(xz[base],                  w.w, acc);
    } else {
        float wj[4] = {w.x, w.y, w.z, w.w};
        #pragma unroll
        for (int j = 0; j < 4; j++) {
            int tt = t - 3 + j;
            if (tt >= 0) acc = fmaf(xz[base + (size_t)(j - 3) * 2 * DINNER], wj[j], acc);
        }
    }
    xc[idx] = acc / (1.f + __expf(-acc));
}

// ---------------------------------------------------------------------------
// ssm projection, split-K x4 with atomicAdd epilogue (outputs pre-zeroed).
// ---------------------------------------------------------------------------
#define KSPLIT 4
#define KRANGE (DINNER / KSPLIT)
__global__ __launch_bounds__(264)
void ssm_proj3(const float* __restrict__ xc, const float* __restrict__ Wx,
               float* __restrict__ Bp, float* __restrict__ Cp,
               float* __restrict__ dt) {
    __shared__ float sW[33 * 132];
    __shared__ float sX[16 * 132];
    int j = threadIdx.x, gy = threadIdx.y;
    int tid = j + 33 * gy;
    int tokbase = blockIdx.x * 16;
    int kbase = blockIdx.y * KRANGE;
    int t0 = gy * 2, t1 = gy * 2 + 1;
    float acc0 = 0.f, acc1 = 0.f;

    for (int kq = 0; kq < KRANGE; kq += 128) {
        int k0 = kbase + kq;
        __syncthreads();
        {
            int row = tid >> 3, l8 = tid & 7;
            const float4* src = (const float4*)(Wx + (size_t)row * DINNER + k0);
            float4* dst = (float4*)(sW + row * 132);
            #pragma unroll
            for (int q = 0; q < 4; q++) dst[q * 8 + l8] = src[q * 8 + l8];
        }
        if (tid < 256) {
            int row = tid >> 4, l16 = tid & 15;
            const float4* src = (const float4*)(xc + (size_t)(tokbase + row) * DINNER + k0);
            float4* dst = (float4*)(sX + row * 132);
            dst[l16] = src[l16];
            dst[16 + l16] = src[16 + l16];
        }
        __syncthreads();
        const float4* wr = (const float4*)(sW + j * 132);
        const float4* x0 = (const float4*)(sX + t0 * 132);
        const float4* x1 = (const float4*)(sX + t1 * 132);
        #pragma unroll 8
        for (int k4 = 0; k4 < 32; k4++) {
            float4 w = wr[k4], a = x0[k4], b = x1[k4];
            acc0 = fmaf(w.x, a.x, acc0); acc0 = fmaf(w.y, a.y, acc0);
            acc0 = fmaf(w.z, a.z, acc0); acc0 = fmaf(w.w, a.w, acc0);
            acc1 = fmaf(w.x, b.x, acc1); acc1 = fmaf(w.y, b.y, acc1);
            acc1 = fmaf(w.z, b.z, acc1); acc1 = fmaf(w.w, b.w, acc1);
        }
    }
    int tok0 = tokbase + t0, tok1 = tokbase + t1;
    if (j < 16)      { atomicAdd(&Bp[tok0 * DSTATE + j], acc0);
                       atomicAdd(&Bp[tok1 * DSTATE + j], acc1); }
    else if (j < 32) { atomicAdd(&Cp[tok0 * DSTATE + j - 16], acc0);
                       atomicAdd(&Cp[tok1 * DSTATE + j - 16], acc1); }
    else             { atomicAdd(&dt[tok0], acc0);
                       atomicAdd(&dt[tok1], acc1); }
}

// ---------------------------------------------------------------------------
// Selective scan + fused softplus(delta) + skip + SiLU(z) gate.
// ---------------------------------------------------------------------------
__global__ __launch_bounds__(256)
void scan_kernel(const float* __restrict__ A_log,
                 const float* __restrict__ Dskip,
                 const float* __restrict__ dtv,
                 const float* __restrict__ Wdt,
                 const float* __restrict__ bdt,
                 const float* __restrict__ xc,
                 const float* __restrict__ Bp,
                 const float* __restrict__ Cp,
                 const float* __restrict__ xz,
                 float* __restrict__ y) {
    int cbase = blockIdx.x * 16;
    int b     = cbase >> 11;
    int dbase = cbase & (DINNER - 1);
    int tid  = threadIdx.x;
    int lane = tid & 31;
    int warp = tid >> 5;
    int half = lane >> 4;
    int n    = lane & 15;
    int c_loc = warp * 2 + half;
    int d = dbase + c_loc;

    float A_n = -__expf(A_log[(size_t)d * DSTATE + n]);
    float Dsk = Dskip[d];
    float h = 0.f;

    int cfill = tid & 15;
    float wdt_c = Wdt[dbase + cfill];
    float bdt_c = bdt[dbase + cfill];

    __shared__ float sB[64][16];
    __shared__ float sC[64][16];
    __shared__ float sD[64][16];
    __shared__ float sX[64][16];
    __shared__ float sZ[64][16];

    const size_t base_t = (size_t)b * 1024;

    for (int t0 = 0; t0 < 1024; t0 += 64) {
        __syncthreads();
        {
            ((float4*)&sB[0][0])[tid] = ((const float4*)(Bp + (base_t + t0) * DSTATE))[tid];
            ((float4*)&sC[0][0])[tid] = ((const float4*)(Cp + (base_t + t0) * DSTATE))[tid];
            int tt = tid >> 2;
            int q  = (tid & 3) * 4;
            size_t r = (base_t + t0 + tt);
            *(float4*)&sX[tt][q] = *(const float4*)(xc + r * DINNER + dbase + q);
            *(float4*)&sZ[tt][q] = *(const float4*)(xz + r * 2 * DINNER + DINNER + dbase + q);
            #pragma unroll
            for (int jj = 0; jj < 4; jj++) {
                int tf = jj * 16 + (tid >> 4);
                float v = fmaf(__ldg(dtv + base_t + t0 + tf), wdt_c, bdt_c);
                sD[tf][cfill] = fmaxf(v, 0.f) + log1pf(__expf(-fabsf(v)));
            }
        }
        __syncthreads();
        #pragma unroll 4
        for (int tt = 0; tt < 64; tt++) {
            float dlt = sD[tt][c_loc];
            float xv  = sX[tt][c_loc];
            float a = __expf(dlt * A_n);
            h = fmaf(a, h, dlt * xv * sB[tt][n]);
            float p = h * sC[tt][n];
            p += __shfl_xor_sync(0xffffffffu, p, 1);
            p += __shfl_xor_sync(0xffffffffu, p, 2);
            p += __shfl_xor_sync(0xffffffffu, p, 4);
            p += __shfl_xor_sync(0xffffffffu, p, 8);
            if (n == 0) {
                float zv = sZ[tt][c_loc];
                float gate = zv / (1.f + __expf(-zv));
                y[(base_t + t0 + tt) * DINNER + d] = f2tf32f((p + xv * Dsk) * gate);
            }
        }
    }
}

// ---------------------------------------------------------------------------
// Launcher
// ---------------------------------------------------------------------------
extern "C" void kernel_launch(void* const* d_in, const int* in_sizes, int n_in,
                              void* d_out, int out_size) {
    const float* x      = (const float*)d_in[0];
    const float* norm_w = (const float*)d_in[1];
    const float* W_in   = (const float*)d_in[2];
    const float* conv_w = (const float*)d_in[3];
    const float* conv_b = (const float*)d_in[4];
    const float* W_x    = (const float*)d_in[5];
    const float* A_log  = (const float*)d_in[6];
    const float* D_skip = (const float*)d_in[7];
    const float* W_dt   = (const float*)d_in[8];
    const float* b_dt   = (const float*)d_in[9];
    const float* W_out  = (const float*)d_in[10];
    float* out = (float*)d_out;

    float *xz, *xc, *Bp, *Cp, *dt, *y, *WoutT;
    __half *xnh, *WinH;
    cudaGetSymbolAddress((void**)&xnh,   g_xnh);
    cudaGetSymbolAddress((void**)&WinH,  g_WinH);
    cudaGetSymbolAddress((void**)&xz,    g_xz);
    cudaGetSymbolAddress((void**)&xc,    g_xc);
    cudaGetSymbolAddress((void**)&Bp,    g_Bp);
    cudaGetSymbolAddress((void**)&Cp,    g_Cp);
    cudaGetSymbolAddress((void**)&dt,    g_dt);
    cudaGetSymbolAddress((void**)&y,     g_y);
    cudaGetSymbolAddress((void**)&WoutT, g_WoutT);

    cudaFuncSetAttribute(gemm_fp16,  cudaFuncAttributeMaxDynamicSharedMemorySize, HSMEM_BYTES);
    cudaFuncSetAttribute(gemm_tf32k, cudaFuncAttributeMaxDynamicSharedMemorySize, GSMEM_BYTES);

    // 0. weight conversion; zero split-K accumulators; seed out = residual
    round_w_kernel<<<(WIN_F4 + WOUT_F4) / 256, 256>>>(W_in, WinH, W_out, WoutT);
    cudaMemsetAsync(Bp, 0, TOKENS * DSTATE * sizeof(float));
    cudaMemsetAsync(Cp, 0, TOKENS * DSTATE * sizeof(float));
    cudaMemsetAsync(dt, 0, TOKENS * sizeof(float));
    cudaMemcpyAsync(out, x, (size_t)TOKENS * DMODEL * sizeof(float),
                    cudaMemcpyDeviceToDevice);
    // 1. RMSNorm (fp16 output)
    rmsnorm_kernel<<<TOKENS, 256>>>(x, norm_w, xnh);
    // 2. xz = xn @ W_in^T   (M=2048, N=4096, K=1024)  fp16 mma, f32 accum
    gemm_fp16<<<dim3(4096 / 128, 2048 / 128), 256, HSMEM_BYTES>>>(
        xnh, WinH, xz, TOKENS, 2 * DINNER, DMODEL);
    // 3. depthwise conv + silu
    conv_silu_kernel<<<TOKENS * DINNER / 256, 256>>>(xz, conv_w, conv_b, xc);
    // 4. B/C/dt projection (split-K x4, atomic reduce)
    ssm_proj3<<<dim3(TOKENS / 16, KSPLIT), dim3(33, 8)>>>(xc, W_x, Bp, Cp, dt);
    // 5. selective scan + fused delta + skip + gate (tf32-rounded y)
    scan_kernel<<<4096 / 16, 256>>>(A_log, D_skip, dt, W_dt, b_dt, xc, Bp, Cp, xz, y);
    // 6. out += y_gated @ W_out^T  (tf32, split-K x2, red.global; out pre-seeded)
    gemm_tf32k<<<dim3(1024 / BN, 2048 / BM, 2), 256, GSMEM_BYTES>>>(
        y, WoutT, out, TOKENS, DMODEL, DINNER);
}